// round 7
// baseline (speedup 1.0000x reference)
#include <cuda_runtime.h>
#include <math.h>

// Problem constants
#define Bsz 64
#define Tsz 512
#define Dsz 512
#define Hsz 1024

// ===================== packed fp32x2 helpers (sm_103a FFMA2) =====================
__device__ __forceinline__ unsigned long long splat2(float f) {
    unsigned long long d;
    unsigned u = __float_as_uint(f);
    asm("mov.b64 %0, {%1, %1};" : "=l"(d) : "r"(u));
    return d;
}
__device__ __forceinline__ void fma2(unsigned long long& d,
                                     unsigned long long a,
                                     unsigned long long b) {
    asm("fma.rn.f32x2 %0, %1, %2, %0;" : "+l"(d) : "l"(a), "l"(b));
}
__device__ __forceinline__ float lo32(unsigned long long v) {
    return __uint_as_float((unsigned)v);
}
__device__ __forceinline__ float hi32(unsigned long long v) {
    return __uint_as_float((unsigned)(v >> 32));
}

// ===================== Phase 1: xin = x @ W_in^T + b_in + bias =====================
// M = B*T = 32768, K = D = 512, N = H = 1024.  Written directly into d_out.
#define BM 64
#define BN 64
#define BK 32

__global__ __launch_bounds__(256) void gemm_in_kernel(
    const float* __restrict__ x, const float* __restrict__ Win,
    const float* __restrict__ bin, const float* __restrict__ bias,
    float* __restrict__ out)
{
    __shared__ __align__(16) float As[BK][BM];   // x^T tile
    __shared__ __align__(16) float Bs[BK][BN];   // W_in^T tile

    const int m0 = blockIdx.y * BM;
    const int n0 = blockIdx.x * BN;
    const int tid = threadIdx.x;          // 256 threads
    const int tx = tid & 15;              // 0..15  (N microtile)
    const int ty = tid >> 4;              // 0..15  (M microtile)

    unsigned long long acc[4][2];
    #pragma unroll
    for (int i = 0; i < 4; i++) { acc[i][0] = 0ULL; acc[i][1] = 0ULL; }

    for (int k0 = 0; k0 < Dsz; k0 += BK) {
        // Load 64x32 x-tile and 64x32 W-tile (transposed into smem).
        #pragma unroll
        for (int i = 0; i < 2; i++) {
            int li = tid + i * 256;        // 0..511 float4 slots
            int r  = li >> 3;              // row 0..63
            int c4 = (li & 7) * 4;         // k offset 0,4,..,28
            float4 v = *(const float4*)&x[(m0 + r) * Dsz + k0 + c4];
            As[c4 + 0][r] = v.x; As[c4 + 1][r] = v.y;
            As[c4 + 2][r] = v.z; As[c4 + 3][r] = v.w;
            float4 u = *(const float4*)&Win[(n0 + r) * Dsz + k0 + c4];
            Bs[c4 + 0][r] = u.x; Bs[c4 + 1][r] = u.y;
            Bs[c4 + 2][r] = u.z; Bs[c4 + 3][r] = u.w;
        }
        __syncthreads();

        #pragma unroll
        for (int kk = 0; kk < BK; kk++) {
            float4 av = *(const float4*)&As[kk][ty * 4];
            ulonglong2 bb = *(const ulonglong2*)&Bs[kk][tx * 4];
            unsigned long long s;
            s = splat2(av.x); fma2(acc[0][0], s, bb.x); fma2(acc[0][1], s, bb.y);
            s = splat2(av.y); fma2(acc[1][0], s, bb.x); fma2(acc[1][1], s, bb.y);
            s = splat2(av.z); fma2(acc[2][0], s, bb.x); fma2(acc[2][1], s, bb.y);
            s = splat2(av.w); fma2(acc[3][0], s, bb.x); fma2(acc[3][1], s, bb.y);
        }
        __syncthreads();
    }

    // Epilogue: add both biases, store (coalesced float4).
    const int n = n0 + tx * 4;
    float bb0 = bin[n + 0] + bias[n + 0];
    float bb1 = bin[n + 1] + bias[n + 1];
    float bb2 = bin[n + 2] + bias[n + 2];
    float bb3 = bin[n + 3] + bias[n + 3];
    #pragma unroll
    for (int i2 = 0; i2 < 4; i2++) {
        int m = m0 + ty * 4 + i2;
        float4 o;
        o.x = lo32(acc[i2][0]) + bb0;
        o.y = hi32(acc[i2][0]) + bb1;
        o.z = lo32(acc[i2][1]) + bb2;
        o.w = hi32(acc[i2][1]) + bb3;
        *(float4*)&out[m * Hsz + n] = o;
    }
}

// ===================== Phase 2: persistent recurrent scan =====================
// out initially holds xin[B,T,H]; each step t overwrites out[:,t,:] with h_t.
// Grid = 2 batch-groups x 64 column-groups = 128 persistent CTAs.
// Each CTA: 32 batches x 16 cols, W_hh slice (1024x16 = 64KB) resident in smem.
#define G2  128
#define NCJ 16      // H-columns per CTA
#define NB  32      // batches per CTA
#define SMEM_P2 ((Hsz * NCJ + 8 * NB * NCJ) * 4)   // 64KB W + 16KB red = 80KB

__device__ unsigned g_count = 0;
__device__ volatile unsigned g_sense = 0;

__global__ __launch_bounds__(256) void rnn_scan_kernel(
    const float* __restrict__ Whh, float* __restrict__ out)
{
    extern __shared__ __align__(16) float sm[];
    float* Ws  = sm;                 // Ws[k*16 + jj] = Whh[(j0+jj)*H + k]
    float* red = sm + Hsz * NCJ;     // red[w*512 + b*16 + jj]

    const int tid  = threadIdx.x;    // 256
    const int w    = tid >> 5;       // warp 0..7 -> k-slice of 128
    const int lane = tid & 31;
    const int tjj  = lane >> 3;      // 0..3  -> 4 j-columns each
    const int tbb  = lane & 7;       // 0..7  -> 4 batch rows each
    const int kw   = w * 128;

    const int bg = blockIdx.x >> 6;  // 0..1  batch group
    const int jg = blockIdx.x & 63;  // 0..63 column group
    const int j0 = jg * NCJ;
    const int b0 = bg * NB;
    const int bbase = b0 + tbb * 4;

    // Preload this CTA's W_hh slice once; reused for all 512 steps.
    for (int idx = tid; idx < Hsz * NCJ; idx += 256) {
        int jj = idx >> 10;              // 0..15
        int k  = idx & 1023;
        Ws[k * NCJ + jj] = Whh[(j0 + jj) * Hsz + k];
    }
    __syncthreads();

    // finalize mapping: thread -> (local batch fb, column pair fjj)
    const int fb  = tid >> 3;            // 0..31
    const int fjj = (tid & 7) * 2;       // 0,2,...,14
    const float* wsBase = Ws + tjj * 4;

    unsigned sense = 0;

    for (int t = 0; t < Tsz; t++) {
        // Prefetch xin for this step (independent of h_{t-1}).
        const size_t xoff = ((size_t)(b0 + fb) * Tsz + t) * Hsz + j0 + fjj;
        float2 xv = *(const float2*)&out[xoff];

        if (t > 0) {
            unsigned long long acc[4][2];
            #pragma unroll
            for (int i = 0; i < 4; i++) { acc[i][0] = 0ULL; acc[i][1] = 0ULL; }

            const float* r0 = out + ((size_t)(bbase + 0) * Tsz + (t - 1)) * Hsz;
            const float* r1 = out + ((size_t)(bbase + 1) * Tsz + (t - 1)) * Hsz;
            const float* r2 = out + ((size_t)(bbase + 2) * Tsz + (t - 1)) * Hsz;
            const float* r3 = out + ((size_t)(bbase + 3) * Tsz + (t - 1)) * Hsz;

            #pragma unroll 4
            for (int k = kw; k < kw + 128; k += 4) {
                float4 h0 = *(const float4*)(r0 + k);
                float4 h1 = *(const float4*)(r1 + k);
                float4 h2 = *(const float4*)(r2 + k);
                float4 h3 = *(const float4*)(r3 + k);
                ulonglong2 wA = *(const ulonglong2*)(wsBase + (k + 0) * NCJ);
                ulonglong2 wB = *(const ulonglong2*)(wsBase + (k + 1) * NCJ);
                ulonglong2 wC = *(const ulonglong2*)(wsBase + (k + 2) * NCJ);
                ulonglong2 wD = *(const ulonglong2*)(wsBase + (k + 3) * NCJ);
                unsigned long long s;

                #define STEP_K(hv, wv)                                   \
                    s = splat2(hv.x ## _UNUSED, 0.f)  /* placeholder */
                #undef STEP_K

                // sub-k 0
                s = splat2(h0.x); fma2(acc[0][0], s, wA.x); fma2(acc[0][1], s, wA.y);
                s = splat2(h1.x); fma2(acc[1][0], s, wA.x); fma2(acc[1][1], s, wA.y);
                s = splat2(h2.x); fma2(acc[2][0], s, wA.x); fma2(acc[2][1], s, wA.y);
                s = splat2(h3.x); fma2(acc[3][0], s, wA.x); fma2(acc[3][1], s, wA.y);
                // sub-k 1
                s = splat2(h0.y); fma2(acc[0][0], s, wB.x); fma2(acc[0][1], s, wB.y);
                s = splat2(h1.y); fma2(acc[1][0], s, wB.x); fma2(acc[1][1], s, wB.y);
                s = splat2(h2.y); fma2(acc[2][0], s, wB.x); fma2(acc[2][1], s, wB.y);
                s = splat2(h3.y); fma2(acc[3][0], s, wB.x); fma2(acc[3][1], s, wB.y);
                // sub-k 2
                s = splat2(h0.z); fma2(acc[0][0], s, wC.x); fma2(acc[0][1], s, wC.y);
                s = splat2(h1.z); fma2(acc[1][0], s, wC.x); fma2(acc[1][1], s, wC.y);
                s = splat2(h2.z); fma2(acc[2][0], s, wC.x); fma2(acc[2][1], s, wC.y);
                s = splat2(h3.z); fma2(acc[3][0], s, wC.x); fma2(acc[3][1], s, wC.y);
                // sub-k 3
                s = splat2(h0.w); fma2(acc[0][0], s, wD.x); fma2(acc[0][1], s, wD.y);
                s = splat2(h1.w); fma2(acc[1][0], s, wD.x); fma2(acc[1][1], s, wD.y);
                s = splat2(h2.w); fma2(acc[2][0], s, wD.x); fma2(acc[2][1], s, wD.y);
                s = splat2(h3.w); fma2(acc[3][0], s, wD.x); fma2(acc[3][1], s, wD.y);
            }

            // Store per-warp partials: red[w][b_local][jj], 8B vector stores.
            #pragma unroll
            for (int r = 0; r < 4; r++) {
                int bl = tbb * 4 + r;
                *(unsigned long long*)&red[w * (NB * NCJ) + bl * NCJ + tjj * 4]     = acc[r][0];
                *(unsigned long long*)&red[w * (NB * NCJ) + bl * NCJ + tjj * 4 + 2] = acc[r][1];
            }
        }
        __syncthreads();

        // Finalize: reduce 8 warp partials, add xin, tanh, write h_t in place.
        float s0 = 0.0f, s1 = 0.0f;
        if (t > 0) {
            #pragma unroll
            for (int ww = 0; ww < 8; ww++) {
                float2 sv = *(const float2*)&red[ww * (NB * NCJ) + fb * NCJ + fjj];
                s0 += sv.x; s1 += sv.y;
            }
        }
        float2 hv;
        hv.x = tanhf(xv.x + s0);
        hv.y = tanhf(xv.y + s1);
        *(float2*)&out[xoff] = hv;

        // gpu-scope fence: publishes h_t AND invalidates L1 (CCTL.IVALL) so the
        // next step's cross-CTA h reads cannot hit stale lines.
        __threadfence();
        __syncthreads();

        // Sense-reversing grid barrier. 512 even toggles -> state returns to
        // {count=0, sense=0} after the kernel, so graph replays are identical.
        if (tid == 0) {
            unsigned s2 = sense ^ 1u;
            unsigned old = atomicAdd(&g_count, 1u);
            if (old == G2 - 1) {
                atomicExch(&g_count, 0u);
                __threadfence();
                g_sense = s2;
            } else {
                while (g_sense != s2) { }
            }
            __threadfence();
        }
        sense ^= 1u;
        __syncthreads();
    }
}

// ===================== launch =====================
extern "C" void kernel_launch(void* const* d_in, const int* in_sizes, int n_in,
                              void* d_out, int out_size)
{
    const float* x    = (const float*)d_in[0];   // [B,T,D]
    const float* Win  = (const float*)d_in[1];   // [H,D]
    const float* bin  = (const float*)d_in[2];   // [H]
    const float* Whh  = (const float*)d_in[3];   // [H,H]
    const float* bias = (const float*)d_in[4];   // [H]
    float* out = (float*)d_out;                  // [B,T,H]

    (void)in_sizes; (void)n_in; (void)out_size;

    // Allow 80KB dynamic smem for the scan kernel (idempotent, capture-safe).
    cudaFuncSetAttribute(rnn_scan_kernel,
                         cudaFuncAttributeMaxDynamicSharedMemorySize, SMEM_P2);

    // Phase 1: xin -> out
    dim3 grid1(Hsz / BN, (Bsz * Tsz) / BM);      // (16, 512)
    gemm_in_kernel<<<grid1, 256>>>(x, Win, bin, bias, out);

    // Phase 2: in-place recurrent scan over T
    rnn_scan_kernel<<<G2, 256, SMEM_P2>>>(Whh, out);
}

// round 8
// speedup vs baseline: 2.0050x; 2.0050x over previous
#include <cuda_runtime.h>
#include <math.h>

// Problem constants
#define Bsz 64
#define Tsz 512
#define Dsz 512
#define Hsz 1024

// ===================== Phase 1: xin = x @ W_in^T + b_in + bias =====================
// M = B*T = 32768, K = D = 512, N = H = 1024.  Written directly into d_out.
// Measured at the scalar-FFMA floor (~1.15ms); keep as-is this round.
#define BM 64
#define BN 64
#define BK 32

__global__ __launch_bounds__(256) void gemm_in_kernel(
    const float* __restrict__ x, const float* __restrict__ Win,
    const float* __restrict__ bin, const float* __restrict__ bias,
    float* __restrict__ out)
{
    __shared__ __align__(16) float As[BK][BM];   // x^T tile
    __shared__ __align__(16) float Bs[BK][BN];   // W_in^T tile

    const int m0 = blockIdx.y * BM;
    const int n0 = blockIdx.x * BN;
    const int tid = threadIdx.x;          // 256 threads
    const int tx = tid & 15;              // 0..15  (N microtile)
    const int ty = tid >> 4;              // 0..15  (M microtile)

    float acc[4][4] = {};

    for (int k0 = 0; k0 < Dsz; k0 += BK) {
        #pragma unroll
        for (int i = 0; i < 2; i++) {
            int li = tid + i * 256;        // 0..511 float4 slots
            int r  = li >> 3;              // row 0..63
            int c4 = (li & 7) * 4;         // k offset 0,4,..,28
            float4 v = *(const float4*)&x[(m0 + r) * Dsz + k0 + c4];
            As[c4 + 0][r] = v.x; As[c4 + 1][r] = v.y;
            As[c4 + 2][r] = v.z; As[c4 + 3][r] = v.w;
            float4 u = *(const float4*)&Win[(n0 + r) * Dsz + k0 + c4];
            Bs[c4 + 0][r] = u.x; Bs[c4 + 1][r] = u.y;
            Bs[c4 + 2][r] = u.z; Bs[c4 + 3][r] = u.w;
        }
        __syncthreads();

        #pragma unroll
        for (int kk = 0; kk < BK; kk++) {
            float4 av = *(const float4*)&As[kk][ty * 4];
            float4 bv = *(const float4*)&Bs[kk][tx * 4];
            float a[4] = {av.x, av.y, av.z, av.w};
            float b[4] = {bv.x, bv.y, bv.z, bv.w};
            #pragma unroll
            for (int i2 = 0; i2 < 4; i2++)
                #pragma unroll
                for (int j = 0; j < 4; j++)
                    acc[i2][j] = fmaf(a[i2], b[j], acc[i2][j]);
        }
        __syncthreads();
    }

    const int n = n0 + tx * 4;
    float bb0 = bin[n + 0] + bias[n + 0];
    float bb1 = bin[n + 1] + bias[n + 1];
    float bb2 = bin[n + 2] + bias[n + 2];
    float bb3 = bin[n + 3] + bias[n + 3];
    #pragma unroll
    for (int i2 = 0; i2 < 4; i2++) {
        int m = m0 + ty * 4 + i2;
        float4 o;
        o.x = acc[i2][0] + bb0;
        o.y = acc[i2][1] + bb1;
        o.z = acc[i2][2] + bb2;
        o.w = acc[i2][3] + bb3;
        *(float4*)&out[m * Hsz + n] = o;
    }
}

// ===================== Phase 2: persistent recurrent scan =====================
// out initially holds xin[B,T,H]; step t overwrites out[:,t,:] with h_t in place.
// Grid = 2 batch-groups x 64 column-groups = 128 persistent CTAs, 512 threads.
// Each CTA: 32 batches x 16 cols; W_hh slice (1024x16 = 64KB) resident in smem.
// 16 warps each own a 64-deep k-slice; partials reduced through smem.
#define G2   128
#define NCJ  16      // H-columns per CTA
#define NB   32      // batches per CTA
#define NW   16      // warps per CTA
#define TPB  512
#define SMEM_P2 ((Hsz * NCJ + NW * NB * NCJ) * 4)   // 64KB W + 32KB red = 96KB

__device__ unsigned g_count = 0;
__device__ volatile unsigned g_sense = 0;

__global__ __launch_bounds__(TPB) void rnn_scan_kernel(
    const float* __restrict__ Whh, float* __restrict__ out)
{
    extern __shared__ __align__(16) float sm[];
    float* Ws  = sm;                 // Ws[k*16 + jj] = Whh[(j0+jj)*H + k]
    float* red = sm + Hsz * NCJ;     // red[w*(NB*NCJ) + b*NCJ + jj]

    const int tid  = threadIdx.x;    // 512
    const int w    = tid >> 5;       // warp 0..15 -> k-slice of 64
    const int lane = tid & 31;
    const int tb   = lane >> 2;      // 0..7  -> 4 batch rows each (32 total)
    const int tj   = lane & 3;       // 0..3  -> 4 j-columns each (16 total)
    const int kw   = w * 64;

    const int bg = blockIdx.x >> 6;  // 0..1  batch group
    const int jg = blockIdx.x & 63;  // 0..63 column group
    const int j0 = jg * NCJ;
    const int b0 = bg * NB;
    const int bbase = b0 + tb * 4;

    // Preload this CTA's W_hh slice once; reused for all 512 steps.
    for (int idx = tid; idx < Hsz * NCJ; idx += TPB) {
        int jj = idx >> 10;              // 0..15
        int k  = idx & 1023;
        Ws[k * NCJ + jj] = Whh[(j0 + jj) * Hsz + k];
    }
    __syncthreads();

    // finalize mapping: one h element per thread
    const int fb = tid >> 4;             // 0..31 local batch
    const int fj = tid & 15;             // 0..15 local column
    const float* wsBase = Ws + tj * 4;

    unsigned sense = 0;

    for (int t = 0; t < Tsz; t++) {
        // Prefetch xin for this step via L2 only (.cg): never pollutes L1 with
        // a pre-tanh sector that the next step's GEMM loads could alias.
        const size_t xoff = ((size_t)(b0 + fb) * Tsz + t) * Hsz + j0 + fj;
        float xv = __ldcg(&out[xoff]);

        if (t > 0) {
            float acc[4][4] = {};
            const float* r0 = out + ((size_t)(bbase + 0) * Tsz + (t - 1)) * Hsz;
            const float* r1 = out + ((size_t)(bbase + 1) * Tsz + (t - 1)) * Hsz;
            const float* r2 = out + ((size_t)(bbase + 2) * Tsz + (t - 1)) * Hsz;
            const float* r3 = out + ((size_t)(bbase + 3) * Tsz + (t - 1)) * Hsz;

            #pragma unroll 4
            for (int k = kw; k < kw + 64; k += 4) {
                float4 h0 = *(const float4*)(r0 + k);
                float4 h1 = *(const float4*)(r1 + k);
                float4 h2 = *(const float4*)(r2 + k);
                float4 h3 = *(const float4*)(r3 + k);
                float4 w0 = *(const float4*)(wsBase + (k + 0) * NCJ);
                float4 w1 = *(const float4*)(wsBase + (k + 1) * NCJ);
                float4 w2 = *(const float4*)(wsBase + (k + 2) * NCJ);
                float4 w3 = *(const float4*)(wsBase + (k + 3) * NCJ);

                #define FMA_ROW(R, hc, wv)                          \
                    acc[R][0] = fmaf(hc, wv.x, acc[R][0]);          \
                    acc[R][1] = fmaf(hc, wv.y, acc[R][1]);          \
                    acc[R][2] = fmaf(hc, wv.z, acc[R][2]);          \
                    acc[R][3] = fmaf(hc, wv.w, acc[R][3]);

                FMA_ROW(0, h0.x, w0) FMA_ROW(0, h0.y, w1) FMA_ROW(0, h0.z, w2) FMA_ROW(0, h0.w, w3)
                FMA_ROW(1, h1.x, w0) FMA_ROW(1, h1.y, w1) FMA_ROW(1, h1.z, w2) FMA_ROW(1, h1.w, w3)
                FMA_ROW(2, h2.x, w0) FMA_ROW(2, h2.y, w1) FMA_ROW(2, h2.z, w2) FMA_ROW(2, h2.w, w3)
                FMA_ROW(3, h3.x, w0) FMA_ROW(3, h3.y, w1) FMA_ROW(3, h3.z, w2) FMA_ROW(3, h3.w, w3)
                #undef FMA_ROW
            }

            // Per-warp partials: red[w][b_local][jj] as float4 stores.
            #pragma unroll
            for (int r = 0; r < 4; r++) {
                int bl = tb * 4 + r;
                *(float4*)&red[w * (NB * NCJ) + bl * NCJ + tj * 4] =
                    make_float4(acc[r][0], acc[r][1], acc[r][2], acc[r][3]);
            }
        }
        __syncthreads();

        // Finalize: reduce 16 warp partials, add xin, tanh, write h_t in place.
        float s = 0.0f;
        if (t > 0) {
            #pragma unroll
            for (int ww = 0; ww < NW; ww++)
                s += red[ww * (NB * NCJ) + fb * NCJ + fj];
        }
        out[xoff] = tanhf(xv + s);

        __syncthreads();   // all STGs of this CTA are CTA-visible to tid 0

        // tid0-only release/acquire + sense-reversing grid barrier.
        // Cumulativity: bar.sync orders all threads' STGs before tid0's
        // membar.gpu, which publishes them chip-wide; the acquire-side
        // threadfence (CCTL.IVALL) also invalidates this SM's L1 so next
        // step's h reads can't hit stale lines.
        if (tid == 0) {
            __threadfence();                       // release
            unsigned s2 = sense ^ 1u;
            unsigned old = atomicAdd(&g_count, 1u);
            if (old == G2 - 1) {
                atomicExch(&g_count, 0u);
                __threadfence();
                g_sense = s2;
            } else {
                while (g_sense != s2) { }
            }
            __threadfence();                       // acquire + L1 inval
        }
        sense ^= 1u;
        __syncthreads();
    }
}

// ===================== launch =====================
extern "C" void kernel_launch(void* const* d_in, const int* in_sizes, int n_in,
                              void* d_out, int out_size)
{
    const float* x    = (const float*)d_in[0];   // [B,T,D]
    const float* Win  = (const float*)d_in[1];   // [H,D]
    const float* bin  = (const float*)d_in[2];   // [H]
    const float* Whh  = (const float*)d_in[3];   // [H,H]
    const float* bias = (const float*)d_in[4];   // [H]
    float* out = (float*)d_out;                  // [B,T,H]

    (void)in_sizes; (void)n_in; (void)out_size;

    // Allow 96KB dynamic smem for the scan kernel (idempotent, capture-safe).
    cudaFuncSetAttribute(rnn_scan_kernel,
                         cudaFuncAttributeMaxDynamicSharedMemorySize, SMEM_P2);

    // Phase 1: xin -> out
    dim3 grid1(Hsz / BN, (Bsz * Tsz) / BM);      // (16, 512)
    gemm_in_kernel<<<grid1, 256>>>(x, Win, bin, bias, out);

    // Phase 2: in-place recurrent scan over T
    rnn_scan_kernel<<<G2, TPB, SMEM_P2>>>(Whh, out);
}

// round 10
// speedup vs baseline: 2.3491x; 1.1717x over previous
#include <cuda_runtime.h>
#include <cuda_fp16.h>
#include <math.h>
#include <stdint.h>

// Problem constants
#define Bsz 64
#define Tsz 512
#define Dsz 512
#define Hsz 1024

// ===================== portable PTX helpers (sm_80+; safe for plain sm_103) ==========
__device__ __forceinline__ uint32_t smem_u32(const void* p) {
    uint32_t a;
    asm("{ .reg .u64 t; cvta.to.shared.u64 t, %1; cvt.u32.u64 %0, t; }" : "=r"(a) : "l"(p));
    return a;
}
__device__ __forceinline__ void ldsm4(uint32_t* r, uint32_t addr) {
    asm volatile("ldmatrix.sync.aligned.m8n8.x4.shared.b16 {%0,%1,%2,%3}, [%4];"
        : "=r"(r[0]), "=r"(r[1]), "=r"(r[2]), "=r"(r[3]) : "r"(addr));
}
__device__ __forceinline__ void mma16816(float* d, const uint32_t* a,
                                         uint32_t b0, uint32_t b1) {
    asm volatile(
        "mma.sync.aligned.m16n8k16.row.col.f32.f16.f16.f32 "
        "{%0,%1,%2,%3}, {%4,%5,%6,%7}, {%8,%9}, {%0,%1,%2,%3};"
        : "+f"(d[0]), "+f"(d[1]), "+f"(d[2]), "+f"(d[3])
        : "r"(a[0]), "r"(a[1]), "r"(a[2]), "r"(a[3]), "r"(b0), "r"(b1));
}
__device__ __forceinline__ void cp16(uint32_t dst, const void* src) {
    asm volatile("cp.async.cg.shared.global [%0], [%1], 16;"
        :: "r"(dst), "l"(src) : "memory");
}
#define CP_COMMIT() asm volatile("cp.async.commit_group;" ::: "memory")
#define CP_WAIT1()  asm volatile("cp.async.wait_group 1;" ::: "memory")
#define CP_WAIT0()  asm volatile("cp.async.wait_group 0;" ::: "memory")

// ===================== global scratch (__device__ arrays — allowed) =====================
// W_hh fp16 hi/lo, pre-swizzled for ldmatrix: 64 slices x (16 j x 1024 k) = 32KB/slice.
__device__ __align__(16) unsigned char g_Wh0[64 * 32768];
__device__ __align__(16) unsigned char g_Wh1[64 * 32768];
// Stacked h splits [rows 0-63: hi, 64-127: lo] x 1024, fp16, ping-pong on t parity.
__device__ __align__(16) __half g_hA[2][128 * Hsz];

// ===================== Prologue: W_hh -> fp16 hi/lo, ldmatrix-swizzled layout ==========
// Within a slice: addr(j,k) = j*2048 + (((k>>3)*16) ^ ((j&7)<<4)) + (k&7)*2
__global__ __launch_bounds__(256) void wsplit_kernel(const float* __restrict__ Whh)
{
    int j = blockIdx.x;                 // 0..1023
    int slice = j >> 4;
    int jr = j & 15;
    unsigned char* b0 = g_Wh0 + (size_t)slice * 32768;
    unsigned char* b1 = g_Wh1 + (size_t)slice * 32768;
    for (int k = threadIdx.x; k < Hsz; k += 256) {
        float v = Whh[j * Hsz + k];
        __half hi = __float2half_rn(v);
        __half lo = __float2half_rn(v - __half2float(hi));
        uint32_t off = (uint32_t)jr * 2048
                     + ((((uint32_t)(k >> 3)) * 16) ^ ((uint32_t)(jr & 7) << 4))
                     + ((k & 7) << 1);
        *(__half*)(b0 + off) = hi;
        *(__half*)(b1 + off) = lo;
    }
}

// ===================== Phase 1: xin = x @ W_in^T + b_in + bias (kept, ~FFMA floor) =====
#define BM 64
#define BN 64
#define BK 32

__global__ __launch_bounds__(256) void gemm_in_kernel(
    const float* __restrict__ x, const float* __restrict__ Win,
    const float* __restrict__ bin, const float* __restrict__ bias,
    float* __restrict__ out)
{
    __shared__ __align__(16) float As[BK][BM];
    __shared__ __align__(16) float Bs[BK][BN];

    const int m0 = blockIdx.y * BM;
    const int n0 = blockIdx.x * BN;
    const int tid = threadIdx.x;
    const int tx = tid & 15;
    const int ty = tid >> 4;

    float acc[4][4] = {};

    for (int k0 = 0; k0 < Dsz; k0 += BK) {
        #pragma unroll
        for (int i = 0; i < 2; i++) {
            int li = tid + i * 256;
            int r  = li >> 3;
            int c4 = (li & 7) * 4;
            float4 v = *(const float4*)&x[(m0 + r) * Dsz + k0 + c4];
            As[c4 + 0][r] = v.x; As[c4 + 1][r] = v.y;
            As[c4 + 2][r] = v.z; As[c4 + 3][r] = v.w;
            float4 u = *(const float4*)&Win[(n0 + r) * Dsz + k0 + c4];
            Bs[c4 + 0][r] = u.x; Bs[c4 + 1][r] = u.y;
            Bs[c4 + 2][r] = u.z; Bs[c4 + 3][r] = u.w;
        }
        __syncthreads();

        #pragma unroll
        for (int kk = 0; kk < BK; kk++) {
            float4 av = *(const float4*)&As[kk][ty * 4];
            float4 bv = *(const float4*)&Bs[kk][tx * 4];
            float a[4] = {av.x, av.y, av.z, av.w};
            float b[4] = {bv.x, bv.y, bv.z, bv.w};
            #pragma unroll
            for (int i2 = 0; i2 < 4; i2++)
                #pragma unroll
                for (int j = 0; j < 4; j++)
                    acc[i2][j] = fmaf(a[i2], b[j], acc[i2][j]);
        }
        __syncthreads();
    }

    const int n = n0 + tx * 4;
    float bb0 = bin[n + 0] + bias[n + 0];
    float bb1 = bin[n + 1] + bias[n + 1];
    float bb2 = bin[n + 2] + bias[n + 2];
    float bb3 = bin[n + 3] + bias[n + 3];
    #pragma unroll
    for (int i2 = 0; i2 < 4; i2++) {
        int m = m0 + ty * 4 + i2;
        float4 o;
        o.x = acc[i2][0] + bb0;
        o.y = acc[i2][1] + bb1;
        o.z = acc[i2][2] + bb2;
        o.w = acc[i2][3] + bb3;
        *(float4*)&out[m * Hsz + n] = o;
    }
}

// ===================== Phase 2: mma.sync recurrent scan =====================
// 64 CTAs x 256 thr; CTA owns 16 j-cols. Per step:
//   D1[128,16] = [h_hi;h_lo] @ W_hi^T ; D2[64,16] = h_hi @ W_lo^T
//   h = tanh(xin + D1[0:64] + D1[64:128] + D2)
#define SG 64

#define SMEM_WHI  0
#define SMEM_WLO  32768
#define SMEM_BUF0 65536
#define SMEM_BUF1 131072
#define SMEM_RED  196608
#define SMEM_TOT  200704     // 192KB tiles + 4KB red

__device__ unsigned g_count = 0;
__device__ volatile unsigned g_sense = 0;

__device__ __forceinline__ void grid_barrier(int tid, unsigned& sense)
{
    __syncthreads();
    if (tid == 0) {
        __threadfence();                       // release this CTA's STGs
        unsigned s2 = sense ^ 1u;
        unsigned old = atomicAdd(&g_count, 1u);
        if (old == SG - 1) {
            atomicExch(&g_count, 0u);
            __threadfence();
            g_sense = s2;
        } else {
            while (g_sense != s2) { }
        }
        __threadfence();                       // acquire (+L1 inval)
    }
    sense ^= 1u;
    __syncthreads();
}

__global__ __launch_bounds__(256) void rnn_scan_mma(float* __restrict__ out)
{
    extern __shared__ __align__(1024) char sm[];
    const uint32_t smb = smem_u32(sm);
    const int tid  = threadIdx.x;
    const int w    = tid >> 5;
    const int lane = tid & 31;
    const int j0   = blockIdx.x * 16;
    const int g    = lane >> 2;          // fragment row group
    const int tt   = lane & 3;           // fragment col group

    // ---- W slices -> SMEM (resident all steps) ----
    {
        const uint4* s0 = (const uint4*)(g_Wh0 + (size_t)blockIdx.x * 32768);
        const uint4* s1 = (const uint4*)(g_Wh1 + (size_t)blockIdx.x * 32768);
        uint4* d0 = (uint4*)(sm + SMEM_WHI);
        uint4* d1 = (uint4*)(sm + SMEM_WLO);
        for (int i = tid; i < 2048; i += 256) { d0[i] = s0[i]; d1[i] = s1[i]; }
    }
    __syncthreads();

    // per-lane ldmatrix constants
    const int mrow = 16 * w + (lane & 15);               // A row (stacked hi/lo)
    const uint32_t a_base = smb + (uint32_t)mrow * 512;  // + buf offset
    const uint32_t a_swz  = (uint32_t)(mrow & 7) << 4;
    const int a_half = lane >> 4;                        // 16B col select
    const int jrow = (lane & 7) + ((lane >> 4) << 3);    // B(j) row
    const uint32_t bhi_base = smb + SMEM_WHI + (uint32_t)jrow * 2048;
    const uint32_t blo_base = smb + SMEM_WLO + (uint32_t)jrow * 2048;
    const uint32_t b_swz = (uint32_t)(jrow & 7) << 4;
    const int b_half = (lane >> 3) & 1;

    float* red = (float*)(sm + SMEM_RED);
    unsigned sense = 0;

    // ---------- t = 0: h = tanh(xin) ----------
    {
        int b = tid >> 2, jq = (tid & 3) * 4;
        size_t o = (size_t)b * (Tsz * Hsz) + j0 + jq;   // t=0
        float4 xv = *(const float4*)&out[o];
        float h0 = tanhf(xv.x), h1 = tanhf(xv.y), h2 = tanhf(xv.z), h3 = tanhf(xv.w);
        *(float4*)&out[o] = make_float4(h0, h1, h2, h3);
        __half a0 = __float2half_rn(h0), a1 = __float2half_rn(h1),
               a2 = __float2half_rn(h2), a3 = __float2half_rn(h3);
        __half2* ph = (__half2*)&g_hA[0][b * Hsz + j0 + jq];
        ph[0] = __halves2half2(a0, a1); ph[1] = __halves2half2(a2, a3);
        __half l0 = __float2half_rn(h0 - __half2float(a0));
        __half l1 = __float2half_rn(h1 - __half2float(a1));
        __half l2 = __float2half_rn(h2 - __half2float(a2));
        __half l3 = __float2half_rn(h3 - __half2float(a3));
        __half2* pl = (__half2*)&g_hA[0][(64 + b) * Hsz + j0 + jq];
        pl[0] = __halves2half2(l0, l1); pl[1] = __halves2half2(l2, l3);
    }
    grid_barrier(tid, sense);

    // ---------- t = 1..511 ----------
    for (int t = 1; t < Tsz; t++) {
        const __half* hrd = g_hA[(t + 1) & 1];
        __half* hwr = g_hA[t & 1];

        // xin prefetch (warps 0-3; same lanes finalize the same elements)
        float2 xv00, xv01, xv10, xv11;
        size_t r0 = 0, r1 = 0;
        if (w < 4) {
            int b = 16 * w + g;
            r0 = ((size_t)b * Tsz + t) * Hsz + j0 + 2 * tt;
            r1 = ((size_t)(b + 8) * Tsz + t) * Hsz + j0 + 2 * tt;
            xv00 = *(const float2*)&out[r0];       // ntile0, rows g
            xv01 = *(const float2*)&out[r1];       // ntile0, rows g+8
            xv10 = *(const float2*)&out[r0 + 8];   // ntile1, rows g
            xv11 = *(const float2*)&out[r1 + 8];   // ntile1, rows g+8
        }

        float dh0[4] = {0,0,0,0}, dh1[4] = {0,0,0,0};   // A x W_hi (ntile0/1)
        float d20[4] = {0,0,0,0}, d21[4] = {0,0,0,0};   // A x W_lo (warps 0-3)

        auto stage = [&](int kc, uint32_t bufoff) {
            const __half* src = hrd + kc * 256;
            #pragma unroll
            for (int s = 0; s < 16; s++) {
                int gg = tid + (s << 8);            // 0..4095 16B granules
                int m = gg >> 5, col = gg & 31;
                uint32_t dst = smb + bufoff + (uint32_t)m * 512
                             + (((uint32_t)col * 16) ^ ((uint32_t)(m & 7) << 4));
                cp16(dst, src + (size_t)m * Hsz + col * 8);
            }
            CP_COMMIT();
        };

        stage(0, SMEM_BUF0);
        #pragma unroll
        for (int kc = 0; kc < 4; kc++) {
            if (kc < 3) {
                stage(kc + 1, (kc & 1) ? SMEM_BUF0 : SMEM_BUF1);
                CP_WAIT1();
            } else {
                CP_WAIT0();
            }
            __syncthreads();
            const uint32_t bufb = (kc & 1) ? SMEM_BUF1 : SMEM_BUF0;
            #pragma unroll
            for (int i = 0; i < 16; i++) {
                uint32_t a[4];
                ldsm4(a, a_base + bufb + (((uint32_t)(2 * i + a_half) * 16) ^ a_swz));
                uint32_t kb = (((uint32_t)(kc * 32 + 2 * i + b_half)) * 16);
                uint32_t bh[4];
                ldsm4(bh, bhi_base + (kb ^ b_swz));
                mma16816(dh0, a, bh[0], bh[1]);
                mma16816(dh1, a, bh[2], bh[3]);
                if (w < 4) {
                    uint32_t bl[4];
                    ldsm4(bl, blo_base + (kb ^ b_swz));
                    mma16816(d20, a, bl[0], bl[1]);
                    mma16816(d21, a, bl[2], bl[3]);
                }
            }
            __syncthreads();   // all reads of bufb done before it is restaged
        }

        // warps 4-7: export h_lo x W_hi partials
        if (w >= 4) {
            int b = 16 * (w - 4) + g;
            *(float2*)&red[b * 16 + 2 * tt]           = make_float2(dh0[0], dh0[1]);
            *(float2*)&red[(b + 8) * 16 + 2 * tt]     = make_float2(dh0[2], dh0[3]);
            *(float2*)&red[b * 16 + 8 + 2 * tt]       = make_float2(dh1[0], dh1[1]);
            *(float2*)&red[(b + 8) * 16 + 8 + 2 * tt] = make_float2(dh1[2], dh1[3]);
        }
        __syncthreads();

        // warps 0-3: combine 3 products + xin, tanh, write out + h splits
        if (w < 4) {
            int b = 16 * w + g;
            float2 rA0 = *(const float2*)&red[b * 16 + 2 * tt];
            float2 rB0 = *(const float2*)&red[(b + 8) * 16 + 2 * tt];
            float2 rA1 = *(const float2*)&red[b * 16 + 8 + 2 * tt];
            float2 rB1 = *(const float2*)&red[(b + 8) * 16 + 8 + 2 * tt];

            float h00 = tanhf(xv00.x + dh0[0] + d20[0] + rA0.x);
            float h01 = tanhf(xv00.y + dh0[1] + d20[1] + rA0.y);
            float h02 = tanhf(xv01.x + dh0[2] + d20[2] + rB0.x);
            float h03 = tanhf(xv01.y + dh0[3] + d20[3] + rB0.y);
            float h10 = tanhf(xv10.x + dh1[0] + d21[0] + rA1.x);
            float h11 = tanhf(xv10.y + dh1[1] + d21[1] + rA1.y);
            float h12 = tanhf(xv11.x + dh1[2] + d21[2] + rB1.x);
            float h13 = tanhf(xv11.y + dh1[3] + d21[3] + rB1.y);

            *(float2*)&out[r0]     = make_float2(h00, h01);
            *(float2*)&out[r1]     = make_float2(h02, h03);
            *(float2*)&out[r0 + 8] = make_float2(h10, h11);
            *(float2*)&out[r1 + 8] = make_float2(h12, h13);

            auto hsplit = [&](float v0, float v1, int row, int jc) {
                __half p0 = __float2half_rn(v0), p1 = __float2half_rn(v1);
                *(__half2*)&hwr[row * Hsz + j0 + jc] = __halves2half2(p0, p1);
                __half q0 = __float2half_rn(v0 - __half2float(p0));
                __half q1 = __float2half_rn(v1 - __half2float(p1));
                *(__half2*)&hwr[(64 + row) * Hsz + j0 + jc] = __halves2half2(q0, q1);
            };
            hsplit(h00, h01, b,     2 * tt);
            hsplit(h02, h03, b + 8, 2 * tt);
            hsplit(h10, h11, b,     8 + 2 * tt);
            hsplit(h12, h13, b + 8, 8 + 2 * tt);
        }

        grid_barrier(tid, sense);   // 1 (t=0) + 511 = 512 toggles -> replay-safe
    }
}

// ===================== launch =====================
extern "C" void kernel_launch(void* const* d_in, const int* in_sizes, int n_in,
                              void* d_out, int out_size)
{
    const float* x    = (const float*)d_in[0];   // [B,T,D]
    const float* Win  = (const float*)d_in[1];   // [H,D]
    const float* bin  = (const float*)d_in[2];   // [H]
    const float* Whh  = (const float*)d_in[3];   // [H,H]
    const float* bias = (const float*)d_in[4];   // [H]
    float* out = (float*)d_out;                  // [B,T,H]

    (void)in_sizes; (void)n_in; (void)out_size;

    cudaFuncSetAttribute(rnn_scan_mma,
                         cudaFuncAttributeMaxDynamicSharedMemorySize, SMEM_TOT);

    // Prologue: W_hh fp16 hi/lo, ldmatrix-swizzled
    wsplit_kernel<<<Hsz, 256>>>(Whh);

    // Phase 1: xin -> out
    dim3 grid1(Hsz / BN, (Bsz * Tsz) / BM);      // (16, 512)
    gemm_in_kernel<<<grid1, 256>>>(x, Win, bin, bias, out);

    // Phase 2: tensor-core (mma.sync) recurrent scan
    rnn_scan_mma<<<SG, 256, SMEM_TOT>>>(out);
}

// round 11
// speedup vs baseline: 2.7462x; 1.1690x over previous
#include <cuda_runtime.h>
#include <cuda_fp16.h>
#include <math.h>
#include <stdint.h>

// Problem constants
#define Bsz 64
#define Tsz 512
#define Dsz 512
#define Hsz 1024

// ===================== portable PTX helpers (sm_80+; safe for plain sm_103) ==========
__device__ __forceinline__ uint32_t smem_u32(const void* p) {
    uint32_t a;
    asm("{ .reg .u64 t; cvta.to.shared.u64 t, %1; cvt.u32.u64 %0, t; }" : "=r"(a) : "l"(p));
    return a;
}
__device__ __forceinline__ void ldsm4(uint32_t* r, uint32_t addr) {
    asm volatile("ldmatrix.sync.aligned.m8n8.x4.shared.b16 {%0,%1,%2,%3}, [%4];"
        : "=r"(r[0]), "=r"(r[1]), "=r"(r[2]), "=r"(r[3]) : "r"(addr));
}
__device__ __forceinline__ void mma16816(float* d, const uint32_t* a,
                                         uint32_t b0, uint32_t b1) {
    asm volatile(
        "mma.sync.aligned.m16n8k16.row.col.f32.f16.f16.f32 "
        "{%0,%1,%2,%3}, {%4,%5,%6,%7}, {%8,%9}, {%0,%1,%2,%3};"
        : "+f"(d[0]), "+f"(d[1]), "+f"(d[2]), "+f"(d[3])
        : "r"(a[0]), "r"(a[1]), "r"(a[2]), "r"(a[3]), "r"(b0), "r"(b1));
}
__device__ __forceinline__ void cp16(uint32_t dst, const void* src) {
    asm volatile("cp.async.cg.shared.global [%0], [%1], 16;"
        :: "r"(dst), "l"(src) : "memory");
}
#define CP_COMMIT() asm volatile("cp.async.commit_group;" ::: "memory")
#define CP_WAIT1()  asm volatile("cp.async.wait_group 1;" ::: "memory")
#define CP_WAIT0()  asm volatile("cp.async.wait_group 0;" ::: "memory")

// ===================== global scratch (__device__ arrays — allowed) =====================
// W_hh fp16 hi/lo, pre-swizzled for ldmatrix: 64 slices x (16 j x 1024 k) = 32KB/slice.
__device__ __align__(16) unsigned char g_Wh0[64 * 32768];
__device__ __align__(16) unsigned char g_Wh1[64 * 32768];
// Stacked h splits [rows 0-63: hi, 64-127: lo] x 1024, fp16, ping-pong on t parity.
__device__ __align__(16) __half g_hA[2][128 * Hsz];
// Phase-1 fp16 splits (row-major, staged+swizzled into SMEM by the GEMM kernel).
__device__ __align__(16) __half g_xhi[32768 * Dsz];
__device__ __align__(16) __half g_xlo[32768 * Dsz];
__device__ __align__(16) __half g_wihi[Hsz * Dsz];
__device__ __align__(16) __half g_wilo[Hsz * Dsz];

// ===================== Prologue: W_hh -> fp16 hi/lo, ldmatrix-swizzled layout ==========
// Within a slice: addr(j,k) = j*2048 + (((k>>3)*16) ^ ((j&7)<<4)) + (k&7)*2
__global__ __launch_bounds__(256) void wsplit_kernel(const float* __restrict__ Whh)
{
    int j = blockIdx.x;                 // 0..1023
    int slice = j >> 4;
    int jr = j & 15;
    unsigned char* b0 = g_Wh0 + (size_t)slice * 32768;
    unsigned char* b1 = g_Wh1 + (size_t)slice * 32768;
    for (int k = threadIdx.x; k < Hsz; k += 256) {
        float v = Whh[j * Hsz + k];
        __half hi = __float2half_rn(v);
        __half lo = __float2half_rn(v - __half2float(hi));
        uint32_t off = (uint32_t)jr * 2048
                     + ((((uint32_t)(k >> 3)) * 16) ^ ((uint32_t)(jr & 7) << 4))
                     + ((k & 7) << 1);
        *(__half*)(b0 + off) = hi;
        *(__half*)(b1 + off) = lo;
    }
}

// ===================== Prologue: x and W_in fp16 hi/lo (row-major) =====================
__global__ __launch_bounds__(256) void xsplit_kernel(const float* __restrict__ x)
{
    size_t i = ((size_t)blockIdx.x * 256 + threadIdx.x) * 4;   // 16384 blocks
    float4 v = *(const float4*)&x[i];
    __half h0 = __float2half_rn(v.x), h1 = __float2half_rn(v.y);
    __half h2 = __float2half_rn(v.z), h3 = __float2half_rn(v.w);
    *(__half2*)&g_xhi[i]     = __halves2half2(h0, h1);
    *(__half2*)&g_xhi[i + 2] = __halves2half2(h2, h3);
    __half l0 = __float2half_rn(v.x - __half2float(h0));
    __half l1 = __float2half_rn(v.y - __half2float(h1));
    __half l2 = __float2half_rn(v.z - __half2float(h2));
    __half l3 = __float2half_rn(v.w - __half2float(h3));
    *(__half2*)&g_xlo[i]     = __halves2half2(l0, l1);
    *(__half2*)&g_xlo[i + 2] = __halves2half2(l2, l3);
}

__global__ __launch_bounds__(256) void winsplit_kernel(const float* __restrict__ Win)
{
    size_t i = ((size_t)blockIdx.x * 256 + threadIdx.x) * 4;   // 512 blocks
    float4 v = *(const float4*)&Win[i];
    __half h0 = __float2half_rn(v.x), h1 = __float2half_rn(v.y);
    __half h2 = __float2half_rn(v.z), h3 = __float2half_rn(v.w);
    *(__half2*)&g_wihi[i]     = __halves2half2(h0, h1);
    *(__half2*)&g_wihi[i + 2] = __halves2half2(h2, h3);
    __half l0 = __float2half_rn(v.x - __half2float(h0));
    __half l1 = __float2half_rn(v.y - __half2float(h1));
    __half l2 = __float2half_rn(v.z - __half2float(h2));
    __half l3 = __float2half_rn(v.w - __half2float(h3));
    *(__half2*)&g_wilo[i]     = __halves2half2(l0, l1);
    *(__half2*)&g_wilo[i + 2] = __halves2half2(l2, l3);
}

// ===================== Phase 1: tensor-core xin GEMM =====================
// out[m][n] = sum_k x[m,k]*Win[n,k] + bin[n] + bias[n]
//           ~= xhi@Whi + xlo@Whi + xhi@Wlo  (fp32 accum)
// CTA tile M128 x N128, k-slab 64, cp.async double buffer.
#define P1_AXHI 0
#define P1_AXLO 16384
#define P1_BWHI 32768
#define P1_BWLO 49152
#define P1_BUFSZ 65536
#define P1_SMEM  131072

__global__ __launch_bounds__(256) void gemm_in_mma(
    const float* __restrict__ bin, const float* __restrict__ bias,
    float* __restrict__ out)
{
    extern __shared__ __align__(1024) char sm[];
    const uint32_t smb = smem_u32(sm);
    const int tid  = threadIdx.x;
    const int w    = tid >> 5;
    const int lane = tid & 31;
    const int m0   = blockIdx.y * 128;
    const int n0   = blockIdx.x * 128;

    const int m_off = (w & 3) * 32;
    const int n_off = (w >> 2) * 64;
    const int g  = lane >> 2;
    const int tt = lane & 3;

    // ldmatrix lane constants (mappings validated by the R10 scan kernel)
    const int arow = m_off + (lane & 15);
    const uint32_t a_swz = (uint32_t)(arow & 7) << 4;
    const int a_half = lane >> 4;
    const int brow = n_off + (lane & 7) + ((lane >> 4) << 3);
    const uint32_t b_swz = (uint32_t)(brow & 7) << 4;
    const int b_half = (lane >> 3) & 1;

    float d[2][8][4];
    #pragma unroll
    for (int mi = 0; mi < 2; mi++)
        #pragma unroll
        for (int nj = 0; nj < 8; nj++)
            #pragma unroll
            for (int q = 0; q < 4; q++) d[mi][nj][q] = 0.0f;

    auto stageP = [&](int s, uint32_t boff) {
        int k0 = s * 64;
        #pragma unroll
        for (int q = 0; q < 4; q++) {
            int gq = tid + q * 256;            // 0..1023 granules (16B)
            int r  = gq >> 3;                  // row 0..127
            int c8 = gq & 7;                   // 8-half granule in row
            uint32_t swz = ((uint32_t)c8 * 16) ^ ((uint32_t)(r & 7) << 4);
            uint32_t rowoff = (uint32_t)r * 128 + swz;
            size_t asrc = (size_t)(m0 + r) * Dsz + k0 + c8 * 8;
            size_t bsrc = (size_t)(n0 + r) * Dsz + k0 + c8 * 8;
            cp16(smb + boff + P1_AXHI + rowoff, g_xhi  + asrc);
            cp16(smb + boff + P1_AXLO + rowoff, g_xlo  + asrc);
            cp16(smb + boff + P1_BWHI + rowoff, g_wihi + bsrc);
            cp16(smb + boff + P1_BWLO + rowoff, g_wilo + bsrc);
        }
        CP_COMMIT();
    };

    stageP(0, 0);
    #pragma unroll 1
    for (int s = 0; s < 8; s++) {
        const uint32_t cb = (s & 1) ? P1_BUFSZ : 0;
        if (s < 7) {
            stageP(s + 1, (s & 1) ? 0 : P1_BUFSZ);
            CP_WAIT1();
        } else {
            CP_WAIT0();
        }
        __syncthreads();

        #pragma unroll
        for (int i = 0; i < 4; i++) {
            const uint32_t kcol = ((uint32_t)(2 * i + a_half) * 16) ^ a_swz;
            const uint32_t kcolb = ((uint32_t)(2 * i + b_half) * 16) ^ b_swz;
            uint32_t axh[2][4], axl[2][4];
            ldsm4(axh[0], smb + cb + P1_AXHI + (uint32_t)arow * 128 + kcol);
            ldsm4(axh[1], smb + cb + P1_AXHI + (uint32_t)(arow + 16) * 128 + kcol);
            ldsm4(axl[0], smb + cb + P1_AXLO + (uint32_t)arow * 128 + kcol);
            ldsm4(axl[1], smb + cb + P1_AXLO + (uint32_t)(arow + 16) * 128 + kcol);
            #pragma unroll
            for (int nt = 0; nt < 4; nt++) {
                uint32_t bwh[4], bwl[4];
                uint32_t boffr = (uint32_t)(brow + nt * 16) * 128;
                ldsm4(bwh, smb + cb + P1_BWHI + boffr + kcolb);
                ldsm4(bwl, smb + cb + P1_BWLO + boffr + kcolb);
                #pragma unroll
                for (int mi = 0; mi < 2; mi++) {
                    mma16816(d[mi][2 * nt],     axh[mi], bwh[0], bwh[1]);
                    mma16816(d[mi][2 * nt + 1], axh[mi], bwh[2], bwh[3]);
                    mma16816(d[mi][2 * nt],     axl[mi], bwh[0], bwh[1]);
                    mma16816(d[mi][2 * nt + 1], axl[mi], bwh[2], bwh[3]);
                    mma16816(d[mi][2 * nt],     axh[mi], bwl[0], bwl[1]);
                    mma16816(d[mi][2 * nt + 1], axh[mi], bwl[2], bwl[3]);
                }
            }
        }
        __syncthreads();
    }

    // Epilogue: add biases, write fp32.
    #pragma unroll
    for (int nj = 0; nj < 8; nj++) {
        int col = n0 + n_off + nj * 8 + 2 * tt;
        float b0 = bin[col]     + bias[col];
        float b1 = bin[col + 1] + bias[col + 1];
        #pragma unroll
        for (int mi = 0; mi < 2; mi++) {
            int row = m0 + m_off + mi * 16 + g;
            *(float2*)&out[(size_t)row * Hsz + col] =
                make_float2(d[mi][nj][0] + b0, d[mi][nj][1] + b1);
            *(float2*)&out[(size_t)(row + 8) * Hsz + col] =
                make_float2(d[mi][nj][2] + b0, d[mi][nj][3] + b1);
        }
    }
}

// ===================== Phase 2: mma.sync recurrent scan (unchanged from R10) ==========
#define SG 64

#define SMEM_WHI  0
#define SMEM_WLO  32768
#define SMEM_BUF0 65536
#define SMEM_BUF1 131072
#define SMEM_RED  196608
#define SMEM_TOT  200704

__device__ unsigned g_count = 0;
__device__ volatile unsigned g_sense = 0;

__device__ __forceinline__ void grid_barrier(int tid, unsigned& sense)
{
    __syncthreads();
    if (tid == 0) {
        __threadfence();
        unsigned s2 = sense ^ 1u;
        unsigned old = atomicAdd(&g_count, 1u);
        if (old == SG - 1) {
            atomicExch(&g_count, 0u);
            __threadfence();
            g_sense = s2;
        } else {
            while (g_sense != s2) { }
        }
        __threadfence();
    }
    sense ^= 1u;
    __syncthreads();
}

__global__ __launch_bounds__(256) void rnn_scan_mma(float* __restrict__ out)
{
    extern __shared__ __align__(1024) char sm[];
    const uint32_t smb = smem_u32(sm);
    const int tid  = threadIdx.x;
    const int w    = tid >> 5;
    const int lane = tid & 31;
    const int j0   = blockIdx.x * 16;
    const int g    = lane >> 2;
    const int tt   = lane & 3;

    {
        const uint4* s0 = (const uint4*)(g_Wh0 + (size_t)blockIdx.x * 32768);
        const uint4* s1 = (const uint4*)(g_Wh1 + (size_t)blockIdx.x * 32768);
        uint4* d0 = (uint4*)(sm + SMEM_WHI);
        uint4* d1 = (uint4*)(sm + SMEM_WLO);
        for (int i = tid; i < 2048; i += 256) { d0[i] = s0[i]; d1[i] = s1[i]; }
    }
    __syncthreads();

    const int mrow = 16 * w + (lane & 15);
    const uint32_t a_base = smb + (uint32_t)mrow * 512;
    const uint32_t a_swz  = (uint32_t)(mrow & 7) << 4;
    const int a_half = lane >> 4;
    const int jrow = (lane & 7) + ((lane >> 4) << 3);
    const uint32_t bhi_base = smb + SMEM_WHI + (uint32_t)jrow * 2048;
    const uint32_t blo_base = smb + SMEM_WLO + (uint32_t)jrow * 2048;
    const uint32_t b_swz = (uint32_t)(jrow & 7) << 4;
    const int b_half = (lane >> 3) & 1;

    float* red = (float*)(sm + SMEM_RED);
    unsigned sense = 0;

    // ---------- t = 0 ----------
    {
        int b = tid >> 2, jq = (tid & 3) * 4;
        size_t o = (size_t)b * (Tsz * Hsz) + j0 + jq;
        float4 xv = *(const float4*)&out[o];
        float h0 = tanhf(xv.x), h1 = tanhf(xv.y), h2 = tanhf(xv.z), h3 = tanhf(xv.w);
        *(float4*)&out[o] = make_float4(h0, h1, h2, h3);
        __half a0 = __float2half_rn(h0), a1 = __float2half_rn(h1),
               a2 = __float2half_rn(h2), a3 = __float2half_rn(h3);
        __half2* ph = (__half2*)&g_hA[0][b * Hsz + j0 + jq];
        ph[0] = __halves2half2(a0, a1); ph[1] = __halves2half2(a2, a3);
        __half l0 = __float2half_rn(h0 - __half2float(a0));
        __half l1 = __float2half_rn(h1 - __half2float(a1));
        __half l2 = __float2half_rn(h2 - __half2float(a2));
        __half l3 = __float2half_rn(h3 - __half2float(a3));
        __half2* pl = (__half2*)&g_hA[0][(64 + b) * Hsz + j0 + jq];
        pl[0] = __halves2half2(l0, l1); pl[1] = __halves2half2(l2, l3);
    }
    grid_barrier(tid, sense);

    // ---------- t = 1..511 ----------
    for (int t = 1; t < Tsz; t++) {
        const __half* hrd = g_hA[(t + 1) & 1];
        __half* hwr = g_hA[t & 1];

        float2 xv00, xv01, xv10, xv11;
        size_t r0 = 0, r1 = 0;
        if (w < 4) {
            int b = 16 * w + g;
            r0 = ((size_t)b * Tsz + t) * Hsz + j0 + 2 * tt;
            r1 = ((size_t)(b + 8) * Tsz + t) * Hsz + j0 + 2 * tt;
            xv00 = *(const float2*)&out[r0];
            xv01 = *(const float2*)&out[r1];
            xv10 = *(const float2*)&out[r0 + 8];
            xv11 = *(const float2*)&out[r1 + 8];
        }

        float dh0[4] = {0,0,0,0}, dh1[4] = {0,0,0,0};
        float d20[4] = {0,0,0,0}, d21[4] = {0,0,0,0};

        auto stage = [&](int kc, uint32_t bufoff) {
            const __half* src = hrd + kc * 256;
            #pragma unroll
            for (int s = 0; s < 16; s++) {
                int gg = tid + (s << 8);
                int m = gg >> 5, col = gg & 31;
                uint32_t dst = smb + bufoff + (uint32_t)m * 512
                             + (((uint32_t)col * 16) ^ ((uint32_t)(m & 7) << 4));
                cp16(dst, src + (size_t)m * Hsz + col * 8);
            }
            CP_COMMIT();
        };

        stage(0, SMEM_BUF0);
        #pragma unroll 1
        for (int kc = 0; kc < 4; kc++) {
            if (kc < 3) {
                stage(kc + 1, (kc & 1) ? SMEM_BUF0 : SMEM_BUF1);
                CP_WAIT1();
            } else {
                CP_WAIT0();
            }
            __syncthreads();
            const uint32_t bufb = (kc & 1) ? SMEM_BUF1 : SMEM_BUF0;
            #pragma unroll
            for (int i = 0; i < 16; i++) {
                uint32_t a[4];
                ldsm4(a, a_base + bufb + (((uint32_t)(2 * i + a_half) * 16) ^ a_swz));
                uint32_t kb = (((uint32_t)(kc * 32 + 2 * i + b_half)) * 16);
                uint32_t bh[4];
                ldsm4(bh, bhi_base + (kb ^ b_swz));
                mma16816(dh0, a, bh[0], bh[1]);
                mma16816(dh1, a, bh[2], bh[3]);
                if (w < 4) {
                    uint32_t bl[4];
                    ldsm4(bl, blo_base + (kb ^ b_swz));
                    mma16816(d20, a, bl[0], bl[1]);
                    mma16816(d21, a, bl[2], bl[3]);
                }
            }
            __syncthreads();
        }

        if (w >= 4) {
            int b = 16 * (w - 4) + g;
            *(float2*)&red[b * 16 + 2 * tt]           = make_float2(dh0[0], dh0[1]);
            *(float2*)&red[(b + 8) * 16 + 2 * tt]     = make_float2(dh0[2], dh0[3]);
            *(float2*)&red[b * 16 + 8 + 2 * tt]       = make_float2(dh1[0], dh1[1]);
            *(float2*)&red[(b + 8) * 16 + 8 + 2 * tt] = make_float2(dh1[2], dh1[3]);
        }
        __syncthreads();

        if (w < 4) {
            int b = 16 * w + g;
            float2 rA0 = *(const float2*)&red[b * 16 + 2 * tt];
            float2 rB0 = *(const float2*)&red[(b + 8) * 16 + 2 * tt];
            float2 rA1 = *(const float2*)&red[b * 16 + 8 + 2 * tt];
            float2 rB1 = *(const float2*)&red[(b + 8) * 16 + 8 + 2 * tt];

            float h00 = tanhf(xv00.x + dh0[0] + d20[0] + rA0.x);
            float h01 = tanhf(xv00.y + dh0[1] + d20[1] + rA0.y);
            float h02 = tanhf(xv01.x + dh0[2] + d20[2] + rB0.x);
            float h03 = tanhf(xv01.y + dh0[3] + d20[3] + rB0.y);
            float h10 = tanhf(xv10.x + dh1[0] + d21[0] + rA1.x);
            float h11 = tanhf(xv10.y + dh1[1] + d21[1] + rA1.y);
            float h12 = tanhf(xv11.x + dh1[2] + d21[2] + rB1.x);
            float h13 = tanhf(xv11.y + dh1[3] + d21[3] + rB1.y);

            *(float2*)&out[r0]     = make_float2(h00, h01);
            *(float2*)&out[r1]     = make_float2(h02, h03);
            *(float2*)&out[r0 + 8] = make_float2(h10, h11);
            *(float2*)&out[r1 + 8] = make_float2(h12, h13);

            auto hsplit = [&](float v0, float v1, int row, int jc) {
                __half p0 = __float2half_rn(v0), p1 = __float2half_rn(v1);
                *(__half2*)&hwr[row * Hsz + j0 + jc] = __halves2half2(p0, p1);
                __half q0 = __float2half_rn(v0 - __half2float(p0));
                __half q1 = __float2half_rn(v1 - __half2float(p1));
                *(__half2*)&hwr[(64 + row) * Hsz + j0 + jc] = __halves2half2(q0, q1);
            };
            hsplit(h00, h01, b,     2 * tt);
            hsplit(h02, h03, b + 8, 2 * tt);
            hsplit(h10, h11, b,     8 + 2 * tt);
            hsplit(h12, h13, b + 8, 8 + 2 * tt);
        }

        grid_barrier(tid, sense);
    }
}

// ===================== launch =====================
extern "C" void kernel_launch(void* const* d_in, const int* in_sizes, int n_in,
                              void* d_out, int out_size)
{
    const float* x    = (const float*)d_in[0];   // [B,T,D]
    const float* Win  = (const float*)d_in[1];   // [H,D]
    const float* bin  = (const float*)d_in[2];   // [H]
    const float* Whh  = (const float*)d_in[3];   // [H,H]
    const float* bias = (const float*)d_in[4];   // [H]
    float* out = (float*)d_out;                  // [B,T,H]

    (void)in_sizes; (void)n_in; (void)out_size;

    cudaFuncSetAttribute(rnn_scan_mma,
                         cudaFuncAttributeMaxDynamicSharedMemorySize, SMEM_TOT);
    cudaFuncSetAttribute(gemm_in_mma,
                         cudaFuncAttributeMaxDynamicSharedMemorySize, P1_SMEM);

    // Prologues: splits (independent kernels)
    wsplit_kernel<<<Hsz, 256>>>(Whh);
    xsplit_kernel<<<16384, 256>>>(x);
    winsplit_kernel<<<512, 256>>>(Win);

    // Phase 1: xin -> out (tensor cores)
    dim3 grid1(8, 256);                          // (N-tiles, M-tiles)
    gemm_in_mma<<<grid1, 256, P1_SMEM>>>(bin, bias, out);

    // Phase 2: tensor-core (mma.sync) recurrent scan
    rnn_scan_mma<<<SG, 256, SMEM_TOT>>>(out);
}

// round 12
// speedup vs baseline: 3.1760x; 1.1565x over previous
#include <cuda_runtime.h>
#include <cuda_fp16.h>
#include <math.h>
#include <stdint.h>

// Problem constants
#define Bsz 64
#define Tsz 512
#define Dsz 512
#define Hsz 1024

// ===================== portable PTX helpers (sm_80+; safe for plain sm_103) ==========
__device__ __forceinline__ uint32_t smem_u32(const void* p) {
    uint32_t a;
    asm("{ .reg .u64 t; cvta.to.shared.u64 t, %1; cvt.u32.u64 %0, t; }" : "=r"(a) : "l"(p));
    return a;
}
__device__ __forceinline__ void ldsm4(uint32_t* r, uint32_t addr) {
    asm volatile("ldmatrix.sync.aligned.m8n8.x4.shared.b16 {%0,%1,%2,%3}, [%4];"
        : "=r"(r[0]), "=r"(r[1]), "=r"(r[2]), "=r"(r[3]) : "r"(addr));
}
__device__ __forceinline__ void mma16816(float* d, const uint32_t* a,
                                         uint32_t b0, uint32_t b1) {
    asm volatile(
        "mma.sync.aligned.m16n8k16.row.col.f32.f16.f16.f32 "
        "{%0,%1,%2,%3}, {%4,%5,%6,%7}, {%8,%9}, {%0,%1,%2,%3};"
        : "+f"(d[0]), "+f"(d[1]), "+f"(d[2]), "+f"(d[3])
        : "r"(a[0]), "r"(a[1]), "r"(a[2]), "r"(a[3]), "r"(b0), "r"(b1));
}
__device__ __forceinline__ void cp16(uint32_t dst, const void* src) {
    asm volatile("cp.async.cg.shared.global [%0], [%1], 16;"
        :: "r"(dst), "l"(src) : "memory");
}
#define CP_COMMIT() asm volatile("cp.async.commit_group;" ::: "memory")
#define CP_WAIT1()  asm volatile("cp.async.wait_group 1;" ::: "memory")
#define CP_WAIT0()  asm volatile("cp.async.wait_group 0;" ::: "memory")

// ===================== global scratch (__device__ arrays — allowed) =====================
// W_hh fp16 hi/lo, ldmatrix-swizzled: 128 slices x (8 j x 1024 k) = 16KB/slice.
__device__ __align__(16) unsigned char g_Wh0[128 * 16384];
__device__ __align__(16) unsigned char g_Wh1[128 * 16384];
// Stacked h splits [rows 0-63: hi, 64-127: lo] x 1024, fp16, ping-pong on t parity.
__device__ __align__(16) __half g_hA[2][128 * Hsz];
// Phase-1 fp16 splits.
__device__ __align__(16) __half g_xhi[32768 * Dsz];
__device__ __align__(16) __half g_xlo[32768 * Dsz];
__device__ __align__(16) __half g_wihi[Hsz * Dsz];
__device__ __align__(16) __half g_wilo[Hsz * Dsz];

// ===================== Prologue: W_hh -> fp16 hi/lo, ldmatrix-swizzled layout ==========
// Within a slice (8 j-rows): addr(jr,k) = jr*2048 + (((k>>3)*16) ^ (jr<<4)) + (k&7)*2
__global__ __launch_bounds__(256) void wsplit_kernel(const float* __restrict__ Whh)
{
    int j = blockIdx.x;                 // 0..1023
    int slice = j >> 3;                 // 0..127
    int jr = j & 7;
    unsigned char* b0 = g_Wh0 + (size_t)slice * 16384;
    unsigned char* b1 = g_Wh1 + (size_t)slice * 16384;
    for (int k = threadIdx.x; k < Hsz; k += 256) {
        float v = Whh[j * Hsz + k];
        __half hi = __float2half_rn(v);
        __half lo = __float2half_rn(v - __half2float(hi));
        uint32_t off = (uint32_t)jr * 2048
                     + ((((uint32_t)(k >> 3)) * 16) ^ ((uint32_t)jr << 4))
                     + ((k & 7) << 1);
        *(__half*)(b0 + off) = hi;
        *(__half*)(b1 + off) = lo;
    }
}

// ===================== Prologue: x and W_in fp16 hi/lo (row-major) =====================
__global__ __launch_bounds__(256) void xsplit_kernel(const float* __restrict__ x)
{
    size_t i = ((size_t)blockIdx.x * 256 + threadIdx.x) * 4;
    float4 v = *(const float4*)&x[i];
    __half h0 = __float2half_rn(v.x), h1 = __float2half_rn(v.y);
    __half h2 = __float2half_rn(v.z), h3 = __float2half_rn(v.w);
    *(__half2*)&g_xhi[i]     = __halves2half2(h0, h1);
    *(__half2*)&g_xhi[i + 2] = __halves2half2(h2, h3);
    __half l0 = __float2half_rn(v.x - __half2float(h0));
    __half l1 = __float2half_rn(v.y - __half2float(h1));
    __half l2 = __float2half_rn(v.z - __half2float(h2));
    __half l3 = __float2half_rn(v.w - __half2float(h3));
    *(__half2*)&g_xlo[i]     = __halves2half2(l0, l1);
    *(__half2*)&g_xlo[i + 2] = __halves2half2(l2, l3);
}

__global__ __launch_bounds__(256) void winsplit_kernel(const float* __restrict__ Win)
{
    size_t i = ((size_t)blockIdx.x * 256 + threadIdx.x) * 4;
    float4 v = *(const float4*)&Win[i];
    __half h0 = __float2half_rn(v.x), h1 = __float2half_rn(v.y);
    __half h2 = __float2half_rn(v.z), h3 = __float2half_rn(v.w);
    *(__half2*)&g_wihi[i]     = __halves2half2(h0, h1);
    *(__half2*)&g_wihi[i + 2] = __halves2half2(h2, h3);
    __half l0 = __float2half_rn(v.x - __half2float(h0));
    __half l1 = __float2half_rn(v.y - __half2float(h1));
    __half l2 = __float2half_rn(v.z - __half2float(h2));
    __half l3 = __float2half_rn(v.w - __half2float(h3));
    *(__half2*)&g_wilo[i]     = __halves2half2(l0, l1);
    *(__half2*)&g_wilo[i + 2] = __halves2half2(l2, l3);
}

// ===================== Phase 1: tensor-core xin GEMM (unchanged from R11) =====
#define P1_AXHI 0
#define P1_AXLO 16384
#define P1_BWHI 32768
#define P1_BWLO 49152
#define P1_BUFSZ 65536
#define P1_SMEM  131072

__global__ __launch_bounds__(256) void gemm_in_mma(
    const float* __restrict__ bin, const float* __restrict__ bias,
    float* __restrict__ out)
{
    extern __shared__ __align__(1024) char sm[];
    const uint32_t smb = smem_u32(sm);
    const int tid  = threadIdx.x;
    const int w    = tid >> 5;
    const int lane = tid & 31;
    const int m0   = blockIdx.y * 128;
    const int n0   = blockIdx.x * 128;

    const int m_off = (w & 3) * 32;
    const int n_off = (w >> 2) * 64;
    const int g  = lane >> 2;
    const int tt = lane & 3;

    const int arow = m_off + (lane & 15);
    const uint32_t a_swz = (uint32_t)(arow & 7) << 4;
    const int a_half = lane >> 4;
    const int brow = n_off + (lane & 7) + ((lane >> 4) << 3);
    const uint32_t b_swz = (uint32_t)(brow & 7) << 4;
    const int b_half = (lane >> 3) & 1;

    float d[2][8][4];
    #pragma unroll
    for (int mi = 0; mi < 2; mi++)
        #pragma unroll
        for (int nj = 0; nj < 8; nj++)
            #pragma unroll
            for (int q = 0; q < 4; q++) d[mi][nj][q] = 0.0f;

    auto stageP = [&](int s, uint32_t boff) {
        int k0 = s * 64;
        #pragma unroll
        for (int q = 0; q < 4; q++) {
            int gq = tid + q * 256;
            int r  = gq >> 3;
            int c8 = gq & 7;
            uint32_t swz = ((uint32_t)c8 * 16) ^ ((uint32_t)(r & 7) << 4);
            uint32_t rowoff = (uint32_t)r * 128 + swz;
            size_t asrc = (size_t)(m0 + r) * Dsz + k0 + c8 * 8;
            size_t bsrc = (size_t)(n0 + r) * Dsz + k0 + c8 * 8;
            cp16(smb + boff + P1_AXHI + rowoff, g_xhi  + asrc);
            cp16(smb + boff + P1_AXLO + rowoff, g_xlo  + asrc);
            cp16(smb + boff + P1_BWHI + rowoff, g_wihi + bsrc);
            cp16(smb + boff + P1_BWLO + rowoff, g_wilo + bsrc);
        }
        CP_COMMIT();
    };

    stageP(0, 0);
    #pragma unroll 1
    for (int s = 0; s < 8; s++) {
        const uint32_t cb = (s & 1) ? P1_BUFSZ : 0;
        if (s < 7) {
            stageP(s + 1, (s & 1) ? 0 : P1_BUFSZ);
            CP_WAIT1();
        } else {
            CP_WAIT0();
        }
        __syncthreads();

        #pragma unroll
        for (int i = 0; i < 4; i++) {
            const uint32_t kcol = ((uint32_t)(2 * i + a_half) * 16) ^ a_swz;
            const uint32_t kcolb = ((uint32_t)(2 * i + b_half) * 16) ^ b_swz;
            uint32_t axh[2][4], axl[2][4];
            ldsm4(axh[0], smb + cb + P1_AXHI + (uint32_t)arow * 128 + kcol);
            ldsm4(axh[1], smb + cb + P1_AXHI + (uint32_t)(arow + 16) * 128 + kcol);
            ldsm4(axl[0], smb + cb + P1_AXLO + (uint32_t)arow * 128 + kcol);
            ldsm4(axl[1], smb + cb + P1_AXLO + (uint32_t)(arow + 16) * 128 + kcol);
            #pragma unroll
            for (int nt = 0; nt < 4; nt++) {
                uint32_t bwh[4], bwl[4];
                uint32_t boffr = (uint32_t)(brow + nt * 16) * 128;
                ldsm4(bwh, smb + cb + P1_BWHI + boffr + kcolb);
                ldsm4(bwl, smb + cb + P1_BWLO + boffr + kcolb);
                #pragma unroll
                for (int mi = 0; mi < 2; mi++) {
                    mma16816(d[mi][2 * nt],     axh[mi], bwh[0], bwh[1]);
                    mma16816(d[mi][2 * nt + 1], axh[mi], bwh[2], bwh[3]);
                    mma16816(d[mi][2 * nt],     axl[mi], bwh[0], bwh[1]);
                    mma16816(d[mi][2 * nt + 1], axl[mi], bwh[2], bwh[3]);
                    mma16816(d[mi][2 * nt],     axh[mi], bwl[0], bwl[1]);
                    mma16816(d[mi][2 * nt + 1], axh[mi], bwl[2], bwl[3]);
                }
            }
        }
        __syncthreads();
    }

    #pragma unroll
    for (int nj = 0; nj < 8; nj++) {
        int col = n0 + n_off + nj * 8 + 2 * tt;
        float b0 = bin[col]     + bias[col];
        float b1 = bin[col + 1] + bias[col + 1];
        #pragma unroll
        for (int mi = 0; mi < 2; mi++) {
            int row = m0 + m_off + mi * 16 + g;
            *(float2*)&out[(size_t)row * Hsz + col] =
                make_float2(d[mi][nj][0] + b0, d[mi][nj][1] + b1);
            *(float2*)&out[(size_t)(row + 8) * Hsz + col] =
                make_float2(d[mi][nj][2] + b0, d[mi][nj][3] + b1);
        }
    }
}

// ===================== Phase 2: mma.sync recurrent scan, 128 CTAs x 8 cols =====
#define SG 128

#define SMEM_WHI  0
#define SMEM_WLO  16384
#define SMEM_BUF0 32768
#define SMEM_BUF1 98304
#define SMEM_RED  163840
#define SMEM_TOT  165888

__device__ unsigned g_count = 0;
__device__ volatile unsigned g_sense = 0;

__device__ __forceinline__ void grid_barrier(int tid, unsigned& sense)
{
    __syncthreads();
    if (tid == 0) {
        __threadfence();
        unsigned s2 = sense ^ 1u;
        unsigned old = atomicAdd(&g_count, 1u);
        if (old == SG - 1) {
            atomicExch(&g_count, 0u);
            __threadfence();
            g_sense = s2;
        } else {
            while (g_sense != s2) { }
        }
        __threadfence();
    }
    sense ^= 1u;
    __syncthreads();
}

__global__ __launch_bounds__(256) void rnn_scan_mma(float* __restrict__ out)
{
    extern __shared__ __align__(1024) char sm[];
    const uint32_t smb = smem_u32(sm);
    const int tid  = threadIdx.x;
    const int w    = tid >> 5;
    const int lane = tid & 31;
    const int j0   = blockIdx.x * 8;
    const int g    = lane >> 2;
    const int tt   = lane & 3;

    // ---- W slices -> SMEM (resident all steps) ----
    {
        const uint4* s0 = (const uint4*)(g_Wh0 + (size_t)blockIdx.x * 16384);
        const uint4* s1 = (const uint4*)(g_Wh1 + (size_t)blockIdx.x * 16384);
        uint4* d0 = (uint4*)(sm + SMEM_WHI);
        uint4* d1 = (uint4*)(sm + SMEM_WLO);
        for (int i = tid; i < 1024; i += 256) { d0[i] = s0[i]; d1[i] = s1[i]; }
    }
    __syncthreads();

    // ldmatrix lane constants
    const int mrow = 16 * w + (lane & 15);               // A row (stacked hi/lo)
    const uint32_t a_base = smb + (uint32_t)mrow * 512;  // + buf offset
    const uint32_t a_swz  = (uint32_t)(mrow & 7) << 4;
    const int a_half = lane >> 4;
    // B x4: lanes 0-7 -> granule 0, 8-15 -> 1, 16-23 -> 2, 24-31 -> 3 (row = lane&7)
    const int jrow = lane & 7;
    const int bgran = lane >> 3;                         // 0..3
    const uint32_t bhi_base = smb + SMEM_WHI + (uint32_t)jrow * 2048;
    const uint32_t blo_base = smb + SMEM_WLO + (uint32_t)jrow * 2048;
    const uint32_t b_swz = (uint32_t)jrow << 4;

    float* red = (float*)(sm + SMEM_RED);
    unsigned sense = 0;

    // ---------- t = 0: h = tanh(xin) ----------
    {
        int b = tid >> 2, jq = (tid & 3) * 2;            // 64 b x 8 cols / 2
        size_t o = (size_t)b * (Tsz * Hsz) + j0 + jq;
        float2 xv = *(const float2*)&out[o];
        float h0 = tanhf(xv.x), h1 = tanhf(xv.y);
        *(float2*)&out[o] = make_float2(h0, h1);
        __half a0 = __float2half_rn(h0), a1 = __float2half_rn(h1);
        *(__half2*)&g_hA[0][b * Hsz + j0 + jq] = __halves2half2(a0, a1);
        __half l0 = __float2half_rn(h0 - __half2float(a0));
        __half l1 = __float2half_rn(h1 - __half2float(a1));
        *(__half2*)&g_hA[0][(64 + b) * Hsz + j0 + jq] = __halves2half2(l0, l1);
    }
    grid_barrier(tid, sense);

    // ---------- t = 1..511 ----------
    for (int t = 1; t < Tsz; t++) {
        const __half* hrd = g_hA[(t + 1) & 1];
        __half* hwr = g_hA[t & 1];

        // xin prefetch (warps 0-3 finalize these elements)
        float2 xv0, xv1;
        size_t r0 = 0, r1 = 0;
        if (w < 4) {
            int b = 16 * w + g;
            r0 = ((size_t)b * Tsz + t) * Hsz + j0 + 2 * tt;
            r1 = ((size_t)(b + 8) * Tsz + t) * Hsz + j0 + 2 * tt;
            xv0 = *(const float2*)&out[r0];
            xv1 = *(const float2*)&out[r1];
        }

        float d[4] = {0, 0, 0, 0};   // hi-row warps: A*(Whi+Wlo); lo-row warps: A*Whi

        auto stage = [&](int kc, uint32_t bufoff) {
            const __half* src = hrd + kc * 256;
            #pragma unroll
            for (int s = 0; s < 16; s++) {
                int gg = tid + (s << 8);
                int m = gg >> 5, col = gg & 31;
                uint32_t dst = smb + bufoff + (uint32_t)m * 512
                             + (((uint32_t)col * 16) ^ ((uint32_t)(m & 7) << 4));
                cp16(dst, src + (size_t)m * Hsz + col * 8);
            }
            CP_COMMIT();
        };

        stage(0, SMEM_BUF0);
        #pragma unroll 1
        for (int kc = 0; kc < 4; kc++) {
            if (kc < 3) {
                stage(kc + 1, (kc & 1) ? SMEM_BUF0 : SMEM_BUF1);
                CP_WAIT1();
            } else {
                CP_WAIT0();
            }
            __syncthreads();
            const uint32_t bufb = (kc & 1) ? SMEM_BUF1 : SMEM_BUF0;
            // 8 double-k-iters per 256-k chunk; one B x4 covers two k-iters.
            #pragma unroll
            for (int ii = 0; ii < 8; ii++) {
                uint32_t kbyte = ((uint32_t)(kc * 32 + 4 * ii + bgran) * 16) ^ b_swz;
                uint32_t bh[4];
                ldsm4(bh, bhi_base + kbyte);
                uint32_t bl[4];
                if (w < 4) ldsm4(bl, blo_base + kbyte);
                #pragma unroll
                for (int s2 = 0; s2 < 2; s2++) {
                    int i = 2 * ii + s2;
                    uint32_t a[4];
                    ldsm4(a, a_base + bufb + (((uint32_t)(2 * i + a_half) * 16) ^ a_swz));
                    mma16816(d, a, bh[2 * s2], bh[2 * s2 + 1]);
                    if (w < 4) mma16816(d, a, bl[2 * s2], bl[2 * s2 + 1]);
                }
            }
            __syncthreads();   // all reads of bufb done before it is restaged
        }

        // warps 4-7: export h_lo x W_hi partials (batches 16(w-4)+g, +8)
        if (w >= 4) {
            int b = 16 * (w - 4) + g;
            *(float2*)&red[b * 8 + 2 * tt]       = make_float2(d[0], d[1]);
            *(float2*)&red[(b + 8) * 8 + 2 * tt] = make_float2(d[2], d[3]);
        }
        __syncthreads();

        // warps 0-3: combine, tanh, write out + h splits
        if (w < 4) {
            int b = 16 * w + g;
            float2 rA = *(const float2*)&red[b * 8 + 2 * tt];
            float2 rB = *(const float2*)&red[(b + 8) * 8 + 2 * tt];

            float h00 = tanhf(xv0.x + d[0] + rA.x);
            float h01 = tanhf(xv0.y + d[1] + rA.y);
            float h10 = tanhf(xv1.x + d[2] + rB.x);
            float h11 = tanhf(xv1.y + d[3] + rB.y);

            *(float2*)&out[r0] = make_float2(h00, h01);
            *(float2*)&out[r1] = make_float2(h10, h11);

            if (t < Tsz - 1) {
                auto hsplit = [&](float v0, float v1, int row) {
                    __half p0 = __float2half_rn(v0), p1 = __float2half_rn(v1);
                    *(__half2*)&hwr[row * Hsz + j0 + 2 * tt] = __halves2half2(p0, p1);
                    __half q0 = __float2half_rn(v0 - __half2float(p0));
                    __half q1 = __float2half_rn(v1 - __half2float(p1));
                    *(__half2*)&hwr[(64 + row) * Hsz + j0 + 2 * tt] = __halves2half2(q0, q1);
                };
                hsplit(h00, h01, b);
                hsplit(h10, h11, b + 8);
            }
        }

        grid_barrier(tid, sense);   // 1 (t=0) + 511 = 512 toggles -> replay-safe
    }
}

// ===================== launch =====================
extern "C" void kernel_launch(void* const* d_in, const int* in_sizes, int n_in,
                              void* d_out, int out_size)
{
    const float* x    = (const float*)d_in[0];   // [B,T,D]
    const float* Win  = (const float*)d_in[1];   // [H,D]
    const float* bin  = (const float*)d_in[2];   // [H]
    const float* Whh  = (const float*)d_in[3];   // [H,H]
    const float* bias = (const float*)d_in[4];   // [H]
    float* out = (float*)d_out;                  // [B,T,H]

    (void)in_sizes; (void)n_in; (void)out_size;

    cudaFuncSetAttribute(rnn_scan_mma,
                         cudaFuncAttributeMaxDynamicSharedMemorySize, SMEM_TOT);
    cudaFuncSetAttribute(gemm_in_mma,
                         cudaFuncAttributeMaxDynamicSharedMemorySize, P1_SMEM);

    // Prologues: splits (independent kernels)
    wsplit_kernel<<<Hsz, 256>>>(Whh);
    xsplit_kernel<<<16384, 256>>>(x);
    winsplit_kernel<<<512, 256>>>(Win);

    // Phase 1: xin -> out (tensor cores)
    dim3 grid1(8, 256);                          // (N-tiles, M-tiles)
    gemm_in_mma<<<grid1, 256, P1_SMEM>>>(bin, bias, out);

    // Phase 2: tensor-core (mma.sync) recurrent scan
    rnn_scan_mma<<<SG, 256, SMEM_TOT>>>(out);
}

// round 13
// speedup vs baseline: 3.5904x; 1.1305x over previous
#include <cuda_runtime.h>
#include <cuda_fp16.h>
#include <math.h>
#include <stdint.h>

// Problem constants
#define Bsz 64
#define Tsz 512
#define Dsz 512
#define Hsz 1024

// ===================== portable PTX helpers (sm_80+; safe for plain sm_103) ==========
__device__ __forceinline__ uint32_t smem_u32(const void* p) {
    uint32_t a;
    asm("{ .reg .u64 t; cvta.to.shared.u64 t, %1; cvt.u32.u64 %0, t; }" : "=r"(a) : "l"(p));
    return a;
}
__device__ __forceinline__ void ldsm4(uint32_t* r, uint32_t addr) {
    asm volatile("ldmatrix.sync.aligned.m8n8.x4.shared.b16 {%0,%1,%2,%3}, [%4];"
        : "=r"(r[0]), "=r"(r[1]), "=r"(r[2]), "=r"(r[3]) : "r"(addr));
}
__device__ __forceinline__ void mma16816(float* d, const uint32_t* a,
                                         uint32_t b0, uint32_t b1) {
    asm volatile(
        "mma.sync.aligned.m16n8k16.row.col.f32.f16.f16.f32 "
        "{%0,%1,%2,%3}, {%4,%5,%6,%7}, {%8,%9}, {%0,%1,%2,%3};"
        : "+f"(d[0]), "+f"(d[1]), "+f"(d[2]), "+f"(d[3])
        : "r"(a[0]), "r"(a[1]), "r"(a[2]), "r"(a[3]), "r"(b0), "r"(b1));
}
__device__ __forceinline__ void cp16(uint32_t dst, const void* src) {
    asm volatile("cp.async.cg.shared.global [%0], [%1], 16;"
        :: "r"(dst), "l"(src) : "memory");
}
#define CP_COMMIT() asm volatile("cp.async.commit_group;" ::: "memory")
#define CP_WAIT1()  asm volatile("cp.async.wait_group 1;" ::: "memory")
#define CP_WAIT0()  asm volatile("cp.async.wait_group 0;" ::: "memory")

// ===================== global scratch (__device__ arrays — allowed) =====================
// W_hh fp16 hi/lo, ldmatrix-swizzled: 32 slices x (32 j x 1024 k) = 64KB/slice.
__device__ __align__(16) unsigned char g_Wh0[32 * 65536];
__device__ __align__(16) unsigned char g_Wh1[32 * 65536];
// Stacked h splits [rows 0-63: hi, 64-127: lo] x 1024, fp16, ping-pong on t parity.
__device__ __align__(16) __half g_hA[2][128 * Hsz];
// Phase-1 fp16 splits.
__device__ __align__(16) __half g_xhi[32768 * Dsz];
__device__ __align__(16) __half g_xlo[32768 * Dsz];
__device__ __align__(16) __half g_wihi[Hsz * Dsz];
__device__ __align__(16) __half g_wilo[Hsz * Dsz];

// ===================== Prologue: W_hh -> fp16 hi/lo, ldmatrix-swizzled layout ==========
// Slice = 32 j-rows; addr(j,k) = (j&31)*2048 + (((k>>3)*16) ^ ((j&7)<<4)) + (k&7)*2
__global__ __launch_bounds__(256) void wsplit_kernel(const float* __restrict__ Whh)
{
    int j = blockIdx.x;                 // 0..1023
    int slice = j >> 5;                 // 0..31
    int jr = j & 31;
    unsigned char* b0 = g_Wh0 + (size_t)slice * 65536;
    unsigned char* b1 = g_Wh1 + (size_t)slice * 65536;
    for (int k = threadIdx.x; k < Hsz; k += 256) {
        float v = Whh[j * Hsz + k];
        __half hi = __float2half_rn(v);
        __half lo = __float2half_rn(v - __half2float(hi));
        uint32_t off = (uint32_t)jr * 2048
                     + ((((uint32_t)(k >> 3)) * 16) ^ ((uint32_t)(jr & 7) << 4))
                     + ((k & 7) << 1);
        *(__half*)(b0 + off) = hi;
        *(__half*)(b1 + off) = lo;
    }
}

// ===================== Prologue: x and W_in fp16 hi/lo (row-major) =====================
__global__ __launch_bounds__(256) void xsplit_kernel(const float* __restrict__ x)
{
    size_t i = ((size_t)blockIdx.x * 256 + threadIdx.x) * 4;
    float4 v = *(const float4*)&x[i];
    __half h0 = __float2half_rn(v.x), h1 = __float2half_rn(v.y);
    __half h2 = __float2half_rn(v.z), h3 = __float2half_rn(v.w);
    *(__half2*)&g_xhi[i]     = __halves2half2(h0, h1);
    *(__half2*)&g_xhi[i + 2] = __halves2half2(h2, h3);
    __half l0 = __float2half_rn(v.x - __half2float(h0));
    __half l1 = __float2half_rn(v.y - __half2float(h1));
    __half l2 = __float2half_rn(v.z - __half2float(h2));
    __half l3 = __float2half_rn(v.w - __half2float(h3));
    *(__half2*)&g_xlo[i]     = __halves2half2(l0, l1);
    *(__half2*)&g_xlo[i + 2] = __halves2half2(l2, l3);
}

__global__ __launch_bounds__(256) void winsplit_kernel(const float* __restrict__ Win)
{
    size_t i = ((size_t)blockIdx.x * 256 + threadIdx.x) * 4;
    float4 v = *(const float4*)&Win[i];
    __half h0 = __float2half_rn(v.x), h1 = __float2half_rn(v.y);
    __half h2 = __float2half_rn(v.z), h3 = __float2half_rn(v.w);
    *(__half2*)&g_wihi[i]     = __halves2half2(h0, h1);
    *(__half2*)&g_wihi[i + 2] = __halves2half2(h2, h3);
    __half l0 = __float2half_rn(v.x - __half2float(h0));
    __half l1 = __float2half_rn(v.y - __half2float(h1));
    __half l2 = __float2half_rn(v.z - __half2float(h2));
    __half l3 = __float2half_rn(v.w - __half2float(h3));
    *(__half2*)&g_wilo[i]     = __halves2half2(l0, l1);
    *(__half2*)&g_wilo[i + 2] = __halves2half2(l2, l3);
}

// ===================== Phase 1: tensor-core xin GEMM (unchanged from R11) =====
#define P1_AXHI 0
#define P1_AXLO 16384
#define P1_BWHI 32768
#define P1_BWLO 49152
#define P1_BUFSZ 65536
#define P1_SMEM  131072

__global__ __launch_bounds__(256) void gemm_in_mma(
    const float* __restrict__ bin, const float* __restrict__ bias,
    float* __restrict__ out)
{
    extern __shared__ __align__(1024) char sm[];
    const uint32_t smb = smem_u32(sm);
    const int tid  = threadIdx.x;
    const int w    = tid >> 5;
    const int lane = tid & 31;
    const int m0   = blockIdx.y * 128;
    const int n0   = blockIdx.x * 128;

    const int m_off = (w & 3) * 32;
    const int n_off = (w >> 2) * 64;
    const int g  = lane >> 2;
    const int tt = lane & 3;

    const int arow = m_off + (lane & 15);
    const uint32_t a_swz = (uint32_t)(arow & 7) << 4;
    const int a_half = lane >> 4;
    const int brow = n_off + (lane & 7) + ((lane >> 4) << 3);
    const uint32_t b_swz = (uint32_t)(brow & 7) << 4;
    const int b_half = (lane >> 3) & 1;

    float d[2][8][4];
    #pragma unroll
    for (int mi = 0; mi < 2; mi++)
        #pragma unroll
        for (int nj = 0; nj < 8; nj++)
            #pragma unroll
            for (int q = 0; q < 4; q++) d[mi][nj][q] = 0.0f;

    auto stageP = [&](int s, uint32_t boff) {
        int k0 = s * 64;
        #pragma unroll
        for (int q = 0; q < 4; q++) {
            int gq = tid + q * 256;
            int r  = gq >> 3;
            int c8 = gq & 7;
            uint32_t swz = ((uint32_t)c8 * 16) ^ ((uint32_t)(r & 7) << 4);
            uint32_t rowoff = (uint32_t)r * 128 + swz;
            size_t asrc = (size_t)(m0 + r) * Dsz + k0 + c8 * 8;
            size_t bsrc = (size_t)(n0 + r) * Dsz + k0 + c8 * 8;
            cp16(smb + boff + P1_AXHI + rowoff, g_xhi  + asrc);
            cp16(smb + boff + P1_AXLO + rowoff, g_xlo  + asrc);
            cp16(smb + boff + P1_BWHI + rowoff, g_wihi + bsrc);
            cp16(smb + boff + P1_BWLO + rowoff, g_wilo + bsrc);
        }
        CP_COMMIT();
    };

    stageP(0, 0);
    #pragma unroll 1
    for (int s = 0; s < 8; s++) {
        const uint32_t cb = (s & 1) ? P1_BUFSZ : 0;
        if (s < 7) {
            stageP(s + 1, (s & 1) ? 0 : P1_BUFSZ);
            CP_WAIT1();
        } else {
            CP_WAIT0();
        }
        __syncthreads();

        #pragma unroll
        for (int i = 0; i < 4; i++) {
            const uint32_t kcol = ((uint32_t)(2 * i + a_half) * 16) ^ a_swz;
            const uint32_t kcolb = ((uint32_t)(2 * i + b_half) * 16) ^ b_swz;
            uint32_t axh[2][4], axl[2][4];
            ldsm4(axh[0], smb + cb + P1_AXHI + (uint32_t)arow * 128 + kcol);
            ldsm4(axh[1], smb + cb + P1_AXHI + (uint32_t)(arow + 16) * 128 + kcol);
            ldsm4(axl[0], smb + cb + P1_AXLO + (uint32_t)arow * 128 + kcol);
            ldsm4(axl[1], smb + cb + P1_AXLO + (uint32_t)(arow + 16) * 128 + kcol);
            #pragma unroll
            for (int nt = 0; nt < 4; nt++) {
                uint32_t bwh[4], bwl[4];
                uint32_t boffr = (uint32_t)(brow + nt * 16) * 128;
                ldsm4(bwh, smb + cb + P1_BWHI + boffr + kcolb);
                ldsm4(bwl, smb + cb + P1_BWLO + boffr + kcolb);
                #pragma unroll
                for (int mi = 0; mi < 2; mi++) {
                    mma16816(d[mi][2 * nt],     axh[mi], bwh[0], bwh[1]);
                    mma16816(d[mi][2 * nt + 1], axh[mi], bwh[2], bwh[3]);
                    mma16816(d[mi][2 * nt],     axl[mi], bwh[0], bwh[1]);
                    mma16816(d[mi][2 * nt + 1], axl[mi], bwh[2], bwh[3]);
                    mma16816(d[mi][2 * nt],     axh[mi], bwl[0], bwl[1]);
                    mma16816(d[mi][2 * nt + 1], axh[mi], bwl[2], bwl[3]);
                }
            }
        }
        __syncthreads();
    }

    #pragma unroll
    for (int nj = 0; nj < 8; nj++) {
        int col = n0 + n_off + nj * 8 + 2 * tt;
        float b0 = bin[col]     + bias[col];
        float b1 = bin[col + 1] + bias[col + 1];
        #pragma unroll
        for (int mi = 0; mi < 2; mi++) {
            int row = m0 + m_off + mi * 16 + g;
            *(float2*)&out[(size_t)row * Hsz + col] =
                make_float2(d[mi][nj][0] + b0, d[mi][nj][1] + b1);
            *(float2*)&out[(size_t)(row + 8) * Hsz + col] =
                make_float2(d[mi][nj][2] + b0, d[mi][nj][3] + b1);
        }
    }
}

// ===================== Phase 2: mma.sync scan, 4 batch-quarters x 32 j-slices =====
// CTA owns 16 batches x 32 j. A = [16 h_hi rows; 16 h_lo rows] x 1024 k (64KB smem,
// staged once per step). W slice (32 j x 1024 k, hi+lo = 128KB) resident all steps.
// Warps: wid>>2 = 0 -> hi rows (x W_hi and W_lo), 1 -> lo rows (x W_hi); wid&3 = n-tile.
#define SG 128

#define SMEM_WHI  0
#define SMEM_WLO  65536
#define SMEM_A    131072
#define SMEM_RED  196608
#define SMEM_TOT  198656

__device__ unsigned g_count = 0;
__device__ volatile unsigned g_sense = 0;

__device__ __forceinline__ void grid_barrier(int tid, unsigned& sense)
{
    __syncthreads();
    if (tid == 0) {
        __threadfence();
        unsigned s2 = sense ^ 1u;
        unsigned old = atomicAdd(&g_count, 1u);
        if (old == SG - 1) {
            atomicExch(&g_count, 0u);
            __threadfence();
            g_sense = s2;
        } else {
            while (g_sense != s2) { }
        }
        __threadfence();
    }
    sense ^= 1u;
    __syncthreads();
}

__global__ __launch_bounds__(256) void rnn_scan_mma(float* __restrict__ out)
{
    extern __shared__ __align__(1024) char sm[];
    const uint32_t smb = smem_u32(sm);
    const int tid  = threadIdx.x;
    const int w    = tid >> 5;
    const int lane = tid & 31;
    const int mi   = w >> 2;             // 0 = hi rows, 1 = lo rows
    const int ni   = w & 3;              // n-tile (8 j each)
    const int g    = lane >> 2;
    const int tt   = lane & 3;

    const int jsl  = blockIdx.x & 31;    // j-slice
    const int j0   = jsl * 32;
    const int b0   = (blockIdx.x >> 5) * 16;   // batch quarter

    // ---- W slice -> SMEM (resident all steps) ----
    {
        const uint4* s0 = (const uint4*)(g_Wh0 + (size_t)jsl * 65536);
        const uint4* s1 = (const uint4*)(g_Wh1 + (size_t)jsl * 65536);
        uint4* d0 = (uint4*)(sm + SMEM_WHI);
        uint4* d1 = (uint4*)(sm + SMEM_WLO);
        for (int i = tid; i < 4096; i += 256) { d0[i] = s0[i]; d1[i] = s1[i]; }
    }
    __syncthreads();

    // ldmatrix lane constants
    const int arow = mi * 16 + (lane & 15);                   // A row 0..31
    const uint32_t a_base = smb + SMEM_A + (uint32_t)arow * 2048;
    const uint32_t a_swz  = (uint32_t)(arow & 7) << 4;
    const int a_half = lane >> 4;
    const int jrow = lane & 7;                                // within warp's 8-j group
    const int bgran = lane >> 3;                              // 0..3
    const uint32_t bhi_base = smb + SMEM_WHI + (uint32_t)(ni * 8 + jrow) * 2048;
    const uint32_t blo_base = smb + SMEM_WLO + (uint32_t)(ni * 8 + jrow) * 2048;
    const uint32_t b_swz = (uint32_t)jrow << 4;

    float* red = (float*)(sm + SMEM_RED);
    unsigned sense = 0;

    // ---------- t = 0: h = tanh(xin) for this CTA's 16b x 32j ----------
    {
        int b  = b0 + (tid >> 4);            // 16 batches
        int jq = (tid & 15) * 2;             // 32 cols / 2
        size_t o = (size_t)b * (Tsz * Hsz) + j0 + jq;
        float2 xv = *(const float2*)&out[o];
        float h0 = tanhf(xv.x), h1 = tanhf(xv.y);
        *(float2*)&out[o] = make_float2(h0, h1);
        __half a0 = __float2half_rn(h0), a1 = __float2half_rn(h1);
        *(__half2*)&g_hA[0][b * Hsz + j0 + jq] = __halves2half2(a0, a1);
        __half l0 = __float2half_rn(h0 - __half2float(a0));
        __half l1 = __float2half_rn(h1 - __half2float(a1));
        *(__half2*)&g_hA[0][(64 + b) * Hsz + j0 + jq] = __halves2half2(l0, l1);
    }
    grid_barrier(tid, sense);

    // ---------- t = 1..511 ----------
    for (int t = 1; t < Tsz; t++) {
        const __half* hrd = g_hA[(t + 1) & 1];
        __half* hwr = g_hA[t & 1];

        // Stage this CTA's A (16 hi + 16 lo rows x 1024 k) in one cp.async batch.
        #pragma unroll
        for (int s = 0; s < 16; s++) {
            int gg = tid + (s << 8);             // 0..4095 granules
            int m  = gg >> 7;                    // A row 0..31
            int c  = gg & 127;                   // k-granule
            int hrow = (m < 16) ? (b0 + m) : (64 + b0 + m - 16);
            uint32_t dst = smb + SMEM_A + (uint32_t)m * 2048
                         + (((uint32_t)c * 16) ^ ((uint32_t)(m & 7) << 4));
            cp16(dst, hrd + (size_t)hrow * Hsz + c * 8);
        }
        CP_COMMIT();

        // xin prefetch (hi warps finalize these elements)
        float2 xv0, xv1;
        size_t r0 = 0, r1 = 0;
        if (mi == 0) {
            int b = b0 + g;
            int col = j0 + ni * 8 + 2 * tt;
            r0 = ((size_t)b * Tsz + t) * Hsz + col;
            r1 = ((size_t)(b + 8) * Tsz + t) * Hsz + col;
            xv0 = *(const float2*)&out[r0];
            xv1 = *(const float2*)&out[r1];
        }

        CP_WAIT0();
        __syncthreads();

        float d[4] = {0, 0, 0, 0};
        // 32 double-k-iters; one B x4 covers two k-iters (k32).
        #pragma unroll 8
        for (int ii = 0; ii < 32; ii++) {
            uint32_t kbyte = ((uint32_t)(4 * ii + bgran) * 16) ^ b_swz;
            uint32_t bh[4];
            ldsm4(bh, bhi_base + kbyte);
            uint32_t bl[4];
            if (mi == 0) ldsm4(bl, blo_base + kbyte);
            #pragma unroll
            for (int s2 = 0; s2 < 2; s2++) {
                int i = 2 * ii + s2;
                uint32_t a[4];
                ldsm4(a, a_base + (((uint32_t)(2 * i + a_half) * 16) ^ a_swz));
                mma16816(d, a, bh[2 * s2], bh[2 * s2 + 1]);
                if (mi == 0) mma16816(d, a, bl[2 * s2], bl[2 * s2 + 1]);
            }
        }

        // lo-row warps export partials (h_lo x W_hi)
        if (mi == 1) {
            *(float4*)&red[(ni * 32 + lane) * 4] = make_float4(d[0], d[1], d[2], d[3]);
        }
        __syncthreads();

        // hi-row warps: combine, tanh, write out + h splits
        if (mi == 0) {
            float4 rr = *(const float4*)&red[(ni * 32 + lane) * 4];

            float h00 = tanhf(xv0.x + d[0] + rr.x);
            float h01 = tanhf(xv0.y + d[1] + rr.y);
            float h10 = tanhf(xv1.x + d[2] + rr.z);
            float h11 = tanhf(xv1.y + d[3] + rr.w);

            *(float2*)&out[r0] = make_float2(h00, h01);
            *(float2*)&out[r1] = make_float2(h10, h11);

            if (t < Tsz - 1) {
                int b = b0 + g;
                int col = j0 + ni * 8 + 2 * tt;
                auto hsplit = [&](float v0, float v1, int row) {
                    __half p0 = __float2half_rn(v0), p1 = __float2half_rn(v1);
                    *(__half2*)&hwr[row * Hsz + col] = __halves2half2(p0, p1);
                    __half q0 = __float2half_rn(v0 - __half2float(p0));
                    __half q1 = __float2half_rn(v1 - __half2float(p1));
                    *(__half2*)&hwr[(64 + row) * Hsz + col] = __halves2half2(q0, q1);
                };
                hsplit(h00, h01, b);
                hsplit(h10, h11, b + 8);
            }
        }

        grid_barrier(tid, sense);   // 1 (t=0) + 511 = 512 toggles -> replay-safe
    }
}

// ===================== launch =====================
extern "C" void kernel_launch(void* const* d_in, const int* in_sizes, int n_in,
                              void* d_out, int out_size)
{
    const float* x    = (const float*)d_in[0];   // [B,T,D]
    const float* Win  = (const float*)d_in[1];   // [H,D]
    const float* bin  = (const float*)d_in[2];   // [H]
    const float* Whh  = (const float*)d_in[3];   // [H,H]
    const float* bias = (const float*)d_in[4];   // [H]
    float* out = (float*)d_out;                  // [B,T,H]

    (void)in_sizes; (void)n_in; (void)out_size;

    cudaFuncSetAttribute(rnn_scan_mma,
                         cudaFuncAttributeMaxDynamicSharedMemorySize, SMEM_TOT);
    cudaFuncSetAttribute(gemm_in_mma,
                         cudaFuncAttributeMaxDynamicSharedMemorySize, P1_SMEM);

    // Prologues: splits (independent kernels)
    wsplit_kernel<<<Hsz, 256>>>(Whh);
    xsplit_kernel<<<16384, 256>>>(x);
    winsplit_kernel<<<512, 256>>>(Win);

    // Phase 1: xin -> out (tensor cores)
    dim3 grid1(8, 256);                          // (N-tiles, M-tiles)
    gemm_in_mma<<<grid1, 256, P1_SMEM>>>(bin, bias, out);

    // Phase 2: tensor-core (mma.sync) recurrent scan
    rnn_scan_mma<<<SG, 256, SMEM_TOT>>>(out);
}

// round 14
// speedup vs baseline: 3.7822x; 1.0534x over previous
#include <cuda_runtime.h>
#include <cuda_fp16.h>
#include <math.h>
#include <stdint.h>

// Problem constants
#define Bsz 64
#define Tsz 512
#define Dsz 512
#define Hsz 1024

// ===================== portable PTX helpers (sm_80+; safe for plain sm_103) ==========
__device__ __forceinline__ uint32_t smem_u32(const void* p) {
    uint32_t a;
    asm("{ .reg .u64 t; cvta.to.shared.u64 t, %1; cvt.u32.u64 %0, t; }" : "=r"(a) : "l"(p));
    return a;
}
__device__ __forceinline__ void ldsm4(uint32_t* r, uint32_t addr) {
    asm volatile("ldmatrix.sync.aligned.m8n8.x4.shared.b16 {%0,%1,%2,%3}, [%4];"
        : "=r"(r[0]), "=r"(r[1]), "=r"(r[2]), "=r"(r[3]) : "r"(addr));
}
__device__ __forceinline__ void mma16816(float* d, const uint32_t* a,
                                         uint32_t b0, uint32_t b1) {
    asm volatile(
        "mma.sync.aligned.m16n8k16.row.col.f32.f16.f16.f32 "
        "{%0,%1,%2,%3}, {%4,%5,%6,%7}, {%8,%9}, {%0,%1,%2,%3};"
        : "+f"(d[0]), "+f"(d[1]), "+f"(d[2]), "+f"(d[3])
        : "r"(a[0]), "r"(a[1]), "r"(a[2]), "r"(a[3]), "r"(b0), "r"(b1));
}
__device__ __forceinline__ void cp16(uint32_t dst, const void* src) {
    asm volatile("cp.async.cg.shared.global [%0], [%1], 16;"
        :: "r"(dst), "l"(src) : "memory");
}
#define CP_COMMIT() asm volatile("cp.async.commit_group;" ::: "memory")
#define CP_WAIT1()  asm volatile("cp.async.wait_group 1;" ::: "memory")
#define CP_WAIT0()  asm volatile("cp.async.wait_group 0;" ::: "memory")

// ===================== global scratch (__device__ arrays — allowed) =====================
// W_hh fp16 hi/lo, ldmatrix-swizzled: 32 slices x (32 j x 1024 k) = 64KB/slice.
__device__ __align__(16) unsigned char g_Wh0[32 * 65536];
__device__ __align__(16) unsigned char g_Wh1[32 * 65536];
// Stacked h splits [rows 0-63: hi, 64-127: lo] x 1024, fp16, ping-pong on t parity.
__device__ __align__(16) __half g_hA[2][128 * Hsz];
// Phase-1 fp16 splits.
__device__ __align__(16) __half g_xhi[32768 * Dsz];
__device__ __align__(16) __half g_xlo[32768 * Dsz];
__device__ __align__(16) __half g_wihi[Hsz * Dsz];
__device__ __align__(16) __half g_wilo[Hsz * Dsz];

// ===================== Prologue: W_hh -> fp16 hi/lo, ldmatrix-swizzled layout ==========
__global__ __launch_bounds__(256) void wsplit_kernel(const float* __restrict__ Whh)
{
    int j = blockIdx.x;                 // 0..1023
    int slice = j >> 5;                 // 0..31
    int jr = j & 31;
    unsigned char* b0 = g_Wh0 + (size_t)slice * 65536;
    unsigned char* b1 = g_Wh1 + (size_t)slice * 65536;
    for (int k = threadIdx.x; k < Hsz; k += 256) {
        float v = Whh[j * Hsz + k];
        __half hi = __float2half_rn(v);
        __half lo = __float2half_rn(v - __half2float(hi));
        uint32_t off = (uint32_t)jr * 2048
                     + ((((uint32_t)(k >> 3)) * 16) ^ ((uint32_t)(jr & 7) << 4))
                     + ((k & 7) << 1);
        *(__half*)(b0 + off) = hi;
        *(__half*)(b1 + off) = lo;
    }
}

// ===================== Prologue: x and W_in fp16 hi/lo (row-major) =====================
__global__ __launch_bounds__(256) void xsplit_kernel(const float* __restrict__ x)
{
    size_t i = ((size_t)blockIdx.x * 256 + threadIdx.x) * 4;
    float4 v = *(const float4*)&x[i];
    __half h0 = __float2half_rn(v.x), h1 = __float2half_rn(v.y);
    __half h2 = __float2half_rn(v.z), h3 = __float2half_rn(v.w);
    *(__half2*)&g_xhi[i]     = __halves2half2(h0, h1);
    *(__half2*)&g_xhi[i + 2] = __halves2half2(h2, h3);
    __half l0 = __float2half_rn(v.x - __half2float(h0));
    __half l1 = __float2half_rn(v.y - __half2float(h1));
    __half l2 = __float2half_rn(v.z - __half2float(h2));
    __half l3 = __float2half_rn(v.w - __half2float(h3));
    *(__half2*)&g_xlo[i]     = __halves2half2(l0, l1);
    *(__half2*)&g_xlo[i + 2] = __halves2half2(l2, l3);
}

__global__ __launch_bounds__(256) void winsplit_kernel(const float* __restrict__ Win)
{
    size_t i = ((size_t)blockIdx.x * 256 + threadIdx.x) * 4;
    float4 v = *(const float4*)&Win[i];
    __half h0 = __float2half_rn(v.x), h1 = __float2half_rn(v.y);
    __half h2 = __float2half_rn(v.z), h3 = __float2half_rn(v.w);
    *(__half2*)&g_wihi[i]     = __halves2half2(h0, h1);
    *(__half2*)&g_wihi[i + 2] = __halves2half2(h2, h3);
    __half l0 = __float2half_rn(v.x - __half2float(h0));
    __half l1 = __float2half_rn(v.y - __half2float(h1));
    __half l2 = __float2half_rn(v.z - __half2float(h2));
    __half l3 = __float2half_rn(v.w - __half2float(h3));
    *(__half2*)&g_wilo[i]     = __halves2half2(l0, l1);
    *(__half2*)&g_wilo[i + 2] = __halves2half2(l2, l3);
}

// ===================== Phase 1: tensor-core xin GEMM (unchanged) =====
#define P1_AXHI 0
#define P1_AXLO 16384
#define P1_BWHI 32768
#define P1_BWLO 49152
#define P1_BUFSZ 65536
#define P1_SMEM  131072

__global__ __launch_bounds__(256) void gemm_in_mma(
    const float* __restrict__ bin, const float* __restrict__ bias,
    float* __restrict__ out)
{
    extern __shared__ __align__(1024) char sm[];
    const uint32_t smb = smem_u32(sm);
    const int tid  = threadIdx.x;
    const int w    = tid >> 5;
    const int lane = tid & 31;
    const int m0   = blockIdx.y * 128;
    const int n0   = blockIdx.x * 128;

    const int m_off = (w & 3) * 32;
    const int n_off = (w >> 2) * 64;
    const int g  = lane >> 2;
    const int tt = lane & 3;

    const int arow = m_off + (lane & 15);
    const uint32_t a_swz = (uint32_t)(arow & 7) << 4;
    const int a_half = lane >> 4;
    const int brow = n_off + (lane & 7) + ((lane >> 4) << 3);
    const uint32_t b_swz = (uint32_t)(brow & 7) << 4;
    const int b_half = (lane >> 3) & 1;

    float d[2][8][4];
    #pragma unroll
    for (int mi = 0; mi < 2; mi++)
        #pragma unroll
        for (int nj = 0; nj < 8; nj++)
            #pragma unroll
            for (int q = 0; q < 4; q++) d[mi][nj][q] = 0.0f;

    auto stageP = [&](int s, uint32_t boff) {
        int k0 = s * 64;
        #pragma unroll
        for (int q = 0; q < 4; q++) {
            int gq = tid + q * 256;
            int r  = gq >> 3;
            int c8 = gq & 7;
            uint32_t swz = ((uint32_t)c8 * 16) ^ ((uint32_t)(r & 7) << 4);
            uint32_t rowoff = (uint32_t)r * 128 + swz;
            size_t asrc = (size_t)(m0 + r) * Dsz + k0 + c8 * 8;
            size_t bsrc = (size_t)(n0 + r) * Dsz + k0 + c8 * 8;
            cp16(smb + boff + P1_AXHI + rowoff, g_xhi  + asrc);
            cp16(smb + boff + P1_AXLO + rowoff, g_xlo  + asrc);
            cp16(smb + boff + P1_BWHI + rowoff, g_wihi + bsrc);
            cp16(smb + boff + P1_BWLO + rowoff, g_wilo + bsrc);
        }
        CP_COMMIT();
    };

    stageP(0, 0);
    #pragma unroll 1
    for (int s = 0; s < 8; s++) {
        const uint32_t cb = (s & 1) ? P1_BUFSZ : 0;
        if (s < 7) {
            stageP(s + 1, (s & 1) ? 0 : P1_BUFSZ);
            CP_WAIT1();
        } else {
            CP_WAIT0();
        }
        __syncthreads();

        #pragma unroll
        for (int i = 0; i < 4; i++) {
            const uint32_t kcol = ((uint32_t)(2 * i + a_half) * 16) ^ a_swz;
            const uint32_t kcolb = ((uint32_t)(2 * i + b_half) * 16) ^ b_swz;
            uint32_t axh[2][4], axl[2][4];
            ldsm4(axh[0], smb + cb + P1_AXHI + (uint32_t)arow * 128 + kcol);
            ldsm4(axh[1], smb + cb + P1_AXHI + (uint32_t)(arow + 16) * 128 + kcol);
            ldsm4(axl[0], smb + cb + P1_AXLO + (uint32_t)arow * 128 + kcol);
            ldsm4(axl[1], smb + cb + P1_AXLO + (uint32_t)(arow + 16) * 128 + kcol);
            #pragma unroll
            for (int nt = 0; nt < 4; nt++) {
                uint32_t bwh[4], bwl[4];
                uint32_t boffr = (uint32_t)(brow + nt * 16) * 128;
                ldsm4(bwh, smb + cb + P1_BWHI + boffr + kcolb);
                ldsm4(bwl, smb + cb + P1_BWLO + boffr + kcolb);
                #pragma unroll
                for (int mi = 0; mi < 2; mi++) {
                    mma16816(d[mi][2 * nt],     axh[mi], bwh[0], bwh[1]);
                    mma16816(d[mi][2 * nt + 1], axh[mi], bwh[2], bwh[3]);
                    mma16816(d[mi][2 * nt],     axl[mi], bwh[0], bwh[1]);
                    mma16816(d[mi][2 * nt + 1], axl[mi], bwh[2], bwh[3]);
                    mma16816(d[mi][2 * nt],     axh[mi], bwl[0], bwl[1]);
                    mma16816(d[mi][2 * nt + 1], axh[mi], bwl[2], bwl[3]);
                }
            }
        }
        __syncthreads();
    }

    #pragma unroll
    for (int nj = 0; nj < 8; nj++) {
        int col = n0 + n_off + nj * 8 + 2 * tt;
        float b0 = bin[col]     + bias[col];
        float b1 = bin[col + 1] + bias[col + 1];
        #pragma unroll
        for (int mi = 0; mi < 2; mi++) {
            int row = m0 + m_off + mi * 16 + g;
            *(float2*)&out[(size_t)row * Hsz + col] =
                make_float2(d[mi][nj][0] + b0, d[mi][nj][1] + b1);
            *(float2*)&out[(size_t)(row + 8) * Hsz + col] =
                make_float2(d[mi][nj][2] + b0, d[mi][nj][3] + b1);
        }
    }
}

// ===================== Phase 2: mma.sync scan, 4 independent batch-quarter groups =====
// CTA owns 16 batches x 32 j.  Dependency closure: a CTA only reads h rows of its own
// batch quarter, written by the 32 CTAs of the same quarter -> per-quarter barriers.
#define SG 128
#define QCTAS 32

#define SMEM_WHI  0
#define SMEM_WLO  65536
#define SMEM_A    131072
#define SMEM_RED  196608
#define SMEM_TOT  198656

// Per-quarter sense-reversing barriers, cache-line padded.
__device__ unsigned g_cnt4[4 * 32];
__device__ volatile unsigned g_sns4[4 * 32];

__device__ __forceinline__ void quarter_barrier(int tid, unsigned& sense, int q)
{
    __syncthreads();
    if (tid == 0) {
        __threadfence();                       // release this CTA's STGs
        unsigned s2 = sense ^ 1u;
        unsigned* cnt = &g_cnt4[q * 32];
        volatile unsigned* sns = &g_sns4[q * 32];
        unsigned old = atomicAdd(cnt, 1u);
        if (old == QCTAS - 1) {
            atomicExch(cnt, 0u);
            __threadfence();
            *sns = s2;
        } else {
            while (*sns != s2) { }
        }
        __threadfence();                       // acquire
    }
    sense ^= 1u;
    __syncthreads();
}

__global__ __launch_bounds__(256) void rnn_scan_mma(float* __restrict__ out)
{
    extern __shared__ __align__(1024) char sm[];
    const uint32_t smb = smem_u32(sm);
    const int tid  = threadIdx.x;
    const int w    = tid >> 5;
    const int lane = tid & 31;
    const int mi   = w >> 2;             // 0 = hi rows, 1 = lo rows
    const int ni   = w & 3;              // n-tile (8 j each)
    const int g    = lane >> 2;
    const int tt   = lane & 3;

    const int jsl  = blockIdx.x & 31;    // j-slice
    const int j0   = jsl * 32;
    const int qid  = blockIdx.x >> 5;    // batch quarter 0..3
    const int b0   = qid * 16;

    // ---- W slice -> SMEM (resident all steps) ----
    {
        const uint4* s0 = (const uint4*)(g_Wh0 + (size_t)jsl * 65536);
        const uint4* s1 = (const uint4*)(g_Wh1 + (size_t)jsl * 65536);
        uint4* d0 = (uint4*)(sm + SMEM_WHI);
        uint4* d1 = (uint4*)(sm + SMEM_WLO);
        for (int i = tid; i < 4096; i += 256) { d0[i] = s0[i]; d1[i] = s1[i]; }
    }
    __syncthreads();

    // ldmatrix lane constants
    const int arow = mi * 16 + (lane & 15);                   // A row 0..31
    const uint32_t a_base = smb + SMEM_A + (uint32_t)arow * 2048;
    const uint32_t a_swz  = (uint32_t)(arow & 7) << 4;
    const int a_half = lane >> 4;
    const int jrow = lane & 7;
    const int bgran = lane >> 3;                              // 0..3
    const uint32_t bhi_base = smb + SMEM_WHI + (uint32_t)(ni * 8 + jrow) * 2048;
    const uint32_t blo_base = smb + SMEM_WLO + (uint32_t)(ni * 8 + jrow) * 2048;
    const uint32_t b_swz = (uint32_t)jrow << 4;

    float* red = (float*)(sm + SMEM_RED);
    unsigned sense = 0;

    // ---------- t = 0: h = tanh(xin) for this CTA's 16b x 32j ----------
    {
        int b  = b0 + (tid >> 4);
        int jq = (tid & 15) * 2;
        size_t o = (size_t)b * (Tsz * Hsz) + j0 + jq;
        float2 xv = *(const float2*)&out[o];
        float h0 = tanhf(xv.x), h1 = tanhf(xv.y);
        *(float2*)&out[o] = make_float2(h0, h1);
        __half a0 = __float2half_rn(h0), a1 = __float2half_rn(h1);
        *(__half2*)&g_hA[0][b * Hsz + j0 + jq] = __halves2half2(a0, a1);
        __half l0 = __float2half_rn(h0 - __half2float(a0));
        __half l1 = __float2half_rn(h1 - __half2float(a1));
        *(__half2*)&g_hA[0][(64 + b) * Hsz + j0 + jq] = __halves2half2(l0, l1);
    }
    quarter_barrier(tid, sense, qid);

    // ---------- t = 1..511 ----------
    for (int t = 1; t < Tsz; t++) {
        const __half* hrd = g_hA[(t + 1) & 1];
        __half* hwr = g_hA[t & 1];

        // Stage A in TWO commit groups (k 0..511, k 512..1023) for latency overlap.
        #pragma unroll
        for (int s = 0; s < 8; s++) {
            int gg = tid + (s << 8);             // 0..2047
            int m  = gg >> 6;                    // A row 0..31
            int c  = gg & 63;                    // k-granule 0..63 (k < 512)
            int hrow = (m < 16) ? (b0 + m) : (64 + b0 + m - 16);
            uint32_t dst = smb + SMEM_A + (uint32_t)m * 2048
                         + (((uint32_t)c * 16) ^ ((uint32_t)(m & 7) << 4));
            cp16(dst, hrd + (size_t)hrow * Hsz + c * 8);
        }
        CP_COMMIT();
        #pragma unroll
        for (int s = 0; s < 8; s++) {
            int gg = tid + (s << 8);
            int m  = gg >> 6;
            int c  = (gg & 63) + 64;             // k-granule 64..127 (k >= 512)
            int hrow = (m < 16) ? (b0 + m) : (64 + b0 + m - 16);
            uint32_t dst = smb + SMEM_A + (uint32_t)m * 2048
                         + (((uint32_t)c * 16) ^ ((uint32_t)(m & 7) << 4));
            cp16(dst, hrd + (size_t)hrow * Hsz + c * 8);
        }
        CP_COMMIT();

        // xin prefetch (hi warps finalize these elements)
        float2 xv0, xv1;
        size_t r0 = 0, r1 = 0;
        if (mi == 0) {
            int b = b0 + g;
            int col = j0 + ni * 8 + 2 * tt;
            r0 = ((size_t)b * Tsz + t) * Hsz + col;
            r1 = ((size_t)(b + 8) * Tsz + t) * Hsz + col;
            xv0 = *(const float2*)&out[r0];
            xv1 = *(const float2*)&out[r1];
        }

        float d[4] = {0, 0, 0, 0};

        // First half: k 0..511 while second half still streams.
        CP_WAIT1();
        __syncthreads();
        #pragma unroll 8
        for (int ii = 0; ii < 16; ii++) {
            uint32_t kbyte = ((uint32_t)(4 * ii + bgran) * 16) ^ b_swz;
            uint32_t bh[4];
            ldsm4(bh, bhi_base + kbyte);
            uint32_t bl[4];
            if (mi == 0) ldsm4(bl, blo_base + kbyte);
            #pragma unroll
            for (int s2 = 0; s2 < 2; s2++) {
                int i = 2 * ii + s2;
                uint32_t a[4];
                ldsm4(a, a_base + (((uint32_t)(2 * i + a_half) * 16) ^ a_swz));
                mma16816(d, a, bh[2 * s2], bh[2 * s2 + 1]);
                if (mi == 0) mma16816(d, a, bl[2 * s2], bl[2 * s2 + 1]);
            }
        }
        // Second half: k 512..1023.
        CP_WAIT0();
        __syncthreads();
        #pragma unroll 8
        for (int ii = 16; ii < 32; ii++) {
            uint32_t kbyte = ((uint32_t)(4 * ii + bgran) * 16) ^ b_swz;
            uint32_t bh[4];
            ldsm4(bh, bhi_base + kbyte);
            uint32_t bl[4];
            if (mi == 0) ldsm4(bl, blo_base + kbyte);
            #pragma unroll
            for (int s2 = 0; s2 < 2; s2++) {
                int i = 2 * ii + s2;
                uint32_t a[4];
                ldsm4(a, a_base + (((uint32_t)(2 * i + a_half) * 16) ^ a_swz));
                mma16816(d, a, bh[2 * s2], bh[2 * s2 + 1]);
                if (mi == 0) mma16816(d, a, bl[2 * s2], bl[2 * s2 + 1]);
            }
        }

        // lo-row warps export partials (h_lo x W_hi)
        if (mi == 1) {
            *(float4*)&red[(ni * 32 + lane) * 4] = make_float4(d[0], d[1], d[2], d[3]);
        }
        __syncthreads();

        // hi-row warps: combine, tanh, write out + h splits
        if (mi == 0) {
            float4 rr = *(const float4*)&red[(ni * 32 + lane) * 4];

            float h00 = tanhf(xv0.x + d[0] + rr.x);
            float h01 = tanhf(xv0.y + d[1] + rr.y);
            float h10 = tanhf(xv1.x + d[2] + rr.z);
            float h11 = tanhf(xv1.y + d[3] + rr.w);

            *(float2*)&out[r0] = make_float2(h00, h01);
            *(float2*)&out[r1] = make_float2(h10, h11);

            if (t < Tsz - 1) {
                int b = b0 + g;
                int col = j0 + ni * 8 + 2 * tt;
                auto hsplit = [&](float v0, float v1, int row) {
                    __half p0 = __float2half_rn(v0), p1 = __float2half_rn(v1);
                    *(__half2*)&hwr[row * Hsz + col] = __halves2half2(p0, p1);
                    __half q0 = __float2half_rn(v0 - __half2float(p0));
                    __half q1 = __float2half_rn(v1 - __half2float(p1));
                    *(__half2*)&hwr[(64 + row) * Hsz + col] = __halves2half2(q0, q1);
                };
                hsplit(h00, h01, b);
                hsplit(h10, h11, b + 8);
            }
        }

        quarter_barrier(tid, sense, qid);   // 512 toggles total -> replay-safe
    }
}

// ===================== launch =====================
extern "C" void kernel_launch(void* const* d_in, const int* in_sizes, int n_in,
                              void* d_out, int out_size)
{
    const float* x    = (const float*)d_in[0];   // [B,T,D]
    const float* Win  = (const float*)d_in[1];   // [H,D]
    const float* bin  = (const float*)d_in[2];   // [H]
    const float* Whh  = (const float*)d_in[3];   // [H,H]
    const float* bias = (const float*)d_in[4];   // [H]
    float* out = (float*)d_out;                  // [B,T,H]

    (void)in_sizes; (void)n_in; (void)out_size;

    cudaFuncSetAttribute(rnn_scan_mma,
                         cudaFuncAttributeMaxDynamicSharedMemorySize, SMEM_TOT);
    cudaFuncSetAttribute(gemm_in_mma,
                         cudaFuncAttributeMaxDynamicSharedMemorySize, P1_SMEM);

    // Prologues: splits (independent kernels)
    wsplit_kernel<<<Hsz, 256>>>(Whh);
    xsplit_kernel<<<16384, 256>>>(x);
    winsplit_kernel<<<512, 256>>>(Win);

    // Phase 1: xin -> out (tensor cores)
    dim3 grid1(8, 256);                          // (N-tiles, M-tiles)
    gemm_in_mma<<<grid1, 256, P1_SMEM>>>(bin, bias, out);

    // Phase 2: tensor-core (mma.sync) recurrent scan
    rnn_scan_mma<<<SG, 256, SMEM_TOT>>>(out);
}

// round 15
// speedup vs baseline: 4.1819x; 1.1057x over previous
#include <cuda_runtime.h>
#include <cuda_fp16.h>
#include <math.h>
#include <stdint.h>

// Problem constants
#define Bsz 64
#define Tsz 512
#define Dsz 512
#define Hsz 1024

// ===================== portable PTX helpers (sm_80+; safe for plain sm_103) ==========
__device__ __forceinline__ uint32_t smem_u32(const void* p) {
    uint32_t a;
    asm("{ .reg .u64 t; cvta.to.shared.u64 t, %1; cvt.u32.u64 %0, t; }" : "=r"(a) : "l"(p));
    return a;
}
__device__ __forceinline__ void ldsm4(uint32_t* r, uint32_t addr) {
    asm volatile("ldmatrix.sync.aligned.m8n8.x4.shared.b16 {%0,%1,%2,%3}, [%4];"
        : "=r"(r[0]), "=r"(r[1]), "=r"(r[2]), "=r"(r[3]) : "r"(addr));
}
__device__ __forceinline__ void mma16816(float* d, const uint32_t* a,
                                         uint32_t b0, uint32_t b1) {
    asm volatile(
        "mma.sync.aligned.m16n8k16.row.col.f32.f16.f16.f32 "
        "{%0,%1,%2,%3}, {%4,%5,%6,%7}, {%8,%9}, {%0,%1,%2,%3};"
        : "+f"(d[0]), "+f"(d[1]), "+f"(d[2]), "+f"(d[3])
        : "r"(a[0]), "r"(a[1]), "r"(a[2]), "r"(a[3]), "r"(b0), "r"(b1));
}
__device__ __forceinline__ void cp16(uint32_t dst, const void* src) {
    asm volatile("cp.async.cg.shared.global [%0], [%1], 16;"
        :: "r"(dst), "l"(src) : "memory");
}
#define CP_COMMIT() asm volatile("cp.async.commit_group;" ::: "memory")
#define CP_WAIT1()  asm volatile("cp.async.wait_group 1;" ::: "memory")
#define CP_WAIT0()  asm volatile("cp.async.wait_group 0;" ::: "memory")

// ===================== global scratch (__device__ arrays — allowed) =====================
// W_hh fp16 hi/lo, ldmatrix-swizzled: 32 slices x (32 j x 1024 k) = 64KB/slice.
__device__ __align__(16) unsigned char g_Wh0[32 * 65536];
__device__ __align__(16) unsigned char g_Wh1[32 * 65536];
// Stacked h splits [rows 0-63: hi, 64-127: lo] x 1024, fp16, ping-pong on t parity.
__device__ __align__(16) __half g_hA[2][128 * Hsz];
// Phase-1 fp16 splits.
__device__ __align__(16) __half g_xhi[32768 * Dsz];
__device__ __align__(16) __half g_xlo[32768 * Dsz];
__device__ __align__(16) __half g_wihi[Hsz * Dsz];
__device__ __align__(16) __half g_wilo[Hsz * Dsz];

// ===================== Prologue: W_hh -> fp16 hi/lo, ldmatrix-swizzled layout ==========
__global__ __launch_bounds__(256) void wsplit_kernel(const float* __restrict__ Whh)
{
    int j = blockIdx.x;                 // 0..1023
    int slice = j >> 5;                 // 0..31
    int jr = j & 31;
    unsigned char* b0 = g_Wh0 + (size_t)slice * 65536;
    unsigned char* b1 = g_Wh1 + (size_t)slice * 65536;
    for (int k = threadIdx.x; k < Hsz; k += 256) {
        float v = Whh[j * Hsz + k];
        __half hi = __float2half_rn(v);
        __half lo = __float2half_rn(v - __half2float(hi));
        uint32_t off = (uint32_t)jr * 2048
                     + ((((uint32_t)(k >> 3)) * 16) ^ ((uint32_t)(jr & 7) << 4))
                     + ((k & 7) << 1);
        *(__half*)(b0 + off) = hi;
        *(__half*)(b1 + off) = lo;
    }
}

// ===================== Prologue: x and W_in fp16 hi/lo (row-major) =====================
__global__ __launch_bounds__(256) void xsplit_kernel(const float* __restrict__ x)
{
    size_t i = ((size_t)blockIdx.x * 256 + threadIdx.x) * 4;
    float4 v = *(const float4*)&x[i];
    __half h0 = __float2half_rn(v.x), h1 = __float2half_rn(v.y);
    __half h2 = __float2half_rn(v.z), h3 = __float2half_rn(v.w);
    *(__half2*)&g_xhi[i]     = __halves2half2(h0, h1);
    *(__half2*)&g_xhi[i + 2] = __halves2half2(h2, h3);
    __half l0 = __float2half_rn(v.x - __half2float(h0));
    __half l1 = __float2half_rn(v.y - __half2float(h1));
    __half l2 = __float2half_rn(v.z - __half2float(h2));
    __half l3 = __float2half_rn(v.w - __half2float(h3));
    *(__half2*)&g_xlo[i]     = __halves2half2(l0, l1);
    *(__half2*)&g_xlo[i + 2] = __halves2half2(l2, l3);
}

__global__ __launch_bounds__(256) void winsplit_kernel(const float* __restrict__ Win)
{
    size_t i = ((size_t)blockIdx.x * 256 + threadIdx.x) * 4;
    float4 v = *(const float4*)&Win[i];
    __half h0 = __float2half_rn(v.x), h1 = __float2half_rn(v.y);
    __half h2 = __float2half_rn(v.z), h3 = __float2half_rn(v.w);
    *(__half2*)&g_wihi[i]     = __halves2half2(h0, h1);
    *(__half2*)&g_wihi[i + 2] = __halves2half2(h2, h3);
    __half l0 = __float2half_rn(v.x - __half2float(h0));
    __half l1 = __float2half_rn(v.y - __half2float(h1));
    __half l2 = __float2half_rn(v.z - __half2float(h2));
    __half l3 = __float2half_rn(v.w - __half2float(h3));
    *(__half2*)&g_wilo[i]     = __halves2half2(l0, l1);
    *(__half2*)&g_wilo[i + 2] = __halves2half2(l2, l3);
}

// ===================== Phase 1: tensor-core xin GEMM (unchanged) =====
#define P1_AXHI 0
#define P1_AXLO 16384
#define P1_BWHI 32768
#define P1_BWLO 49152
#define P1_BUFSZ 65536
#define P1_SMEM  131072

__global__ __launch_bounds__(256) void gemm_in_mma(
    const float* __restrict__ bin, const float* __restrict__ bias,
    float* __restrict__ out)
{
    extern __shared__ __align__(1024) char sm[];
    const uint32_t smb = smem_u32(sm);
    const int tid  = threadIdx.x;
    const int w    = tid >> 5;
    const int lane = tid & 31;
    const int m0   = blockIdx.y * 128;
    const int n0   = blockIdx.x * 128;

    const int m_off = (w & 3) * 32;
    const int n_off = (w >> 2) * 64;
    const int g  = lane >> 2;
    const int tt = lane & 3;

    const int arow = m_off + (lane & 15);
    const uint32_t a_swz = (uint32_t)(arow & 7) << 4;
    const int a_half = lane >> 4;
    const int brow = n_off + (lane & 7) + ((lane >> 4) << 3);
    const uint32_t b_swz = (uint32_t)(brow & 7) << 4;
    const int b_half = (lane >> 3) & 1;

    float d[2][8][4];
    #pragma unroll
    for (int mi = 0; mi < 2; mi++)
        #pragma unroll
        for (int nj = 0; nj < 8; nj++)
            #pragma unroll
            for (int q = 0; q < 4; q++) d[mi][nj][q] = 0.0f;

    auto stageP = [&](int s, uint32_t boff) {
        int k0 = s * 64;
        #pragma unroll
        for (int q = 0; q < 4; q++) {
            int gq = tid + q * 256;
            int r  = gq >> 3;
            int c8 = gq & 7;
            uint32_t swz = ((uint32_t)c8 * 16) ^ ((uint32_t)(r & 7) << 4);
            uint32_t rowoff = (uint32_t)r * 128 + swz;
            size_t asrc = (size_t)(m0 + r) * Dsz + k0 + c8 * 8;
            size_t bsrc = (size_t)(n0 + r) * Dsz + k0 + c8 * 8;
            cp16(smb + boff + P1_AXHI + rowoff, g_xhi  + asrc);
            cp16(smb + boff + P1_AXLO + rowoff, g_xlo  + asrc);
            cp16(smb + boff + P1_BWHI + rowoff, g_wihi + bsrc);
            cp16(smb + boff + P1_BWLO + rowoff, g_wilo + bsrc);
        }
        CP_COMMIT();
    };

    stageP(0, 0);
    #pragma unroll 1
    for (int s = 0; s < 8; s++) {
        const uint32_t cb = (s & 1) ? P1_BUFSZ : 0;
        if (s < 7) {
            stageP(s + 1, (s & 1) ? 0 : P1_BUFSZ);
            CP_WAIT1();
        } else {
            CP_WAIT0();
        }
        __syncthreads();

        #pragma unroll
        for (int i = 0; i < 4; i++) {
            const uint32_t kcol = ((uint32_t)(2 * i + a_half) * 16) ^ a_swz;
            const uint32_t kcolb = ((uint32_t)(2 * i + b_half) * 16) ^ b_swz;
            uint32_t axh[2][4], axl[2][4];
            ldsm4(axh[0], smb + cb + P1_AXHI + (uint32_t)arow * 128 + kcol);
            ldsm4(axh[1], smb + cb + P1_AXHI + (uint32_t)(arow + 16) * 128 + kcol);
            ldsm4(axl[0], smb + cb + P1_AXLO + (uint32_t)arow * 128 + kcol);
            ldsm4(axl[1], smb + cb + P1_AXLO + (uint32_t)(arow + 16) * 128 + kcol);
            #pragma unroll
            for (int nt = 0; nt < 4; nt++) {
                uint32_t bwh[4], bwl[4];
                uint32_t boffr = (uint32_t)(brow + nt * 16) * 128;
                ldsm4(bwh, smb + cb + P1_BWHI + boffr + kcolb);
                ldsm4(bwl, smb + cb + P1_BWLO + boffr + kcolb);
                #pragma unroll
                for (int mi = 0; mi < 2; mi++) {
                    mma16816(d[mi][2 * nt],     axh[mi], bwh[0], bwh[1]);
                    mma16816(d[mi][2 * nt + 1], axh[mi], bwh[2], bwh[3]);
                    mma16816(d[mi][2 * nt],     axl[mi], bwh[0], bwh[1]);
                    mma16816(d[mi][2 * nt + 1], axl[mi], bwh[2], bwh[3]);
                    mma16816(d[mi][2 * nt],     axh[mi], bwl[0], bwl[1]);
                    mma16816(d[mi][2 * nt + 1], axh[mi], bwl[2], bwl[3]);
                }
            }
        }
        __syncthreads();
    }

    #pragma unroll
    for (int nj = 0; nj < 8; nj++) {
        int col = n0 + n_off + nj * 8 + 2 * tt;
        float b0 = bin[col]     + bias[col];
        float b1 = bin[col + 1] + bias[col + 1];
        #pragma unroll
        for (int mi = 0; mi < 2; mi++) {
            int row = m0 + m_off + mi * 16 + g;
            *(float2*)&out[(size_t)row * Hsz + col] =
                make_float2(d[mi][nj][0] + b0, d[mi][nj][1] + b1);
            *(float2*)&out[(size_t)(row + 8) * Hsz + col] =
                make_float2(d[mi][nj][2] + b0, d[mi][nj][3] + b1);
        }
    }
}

// ===================== Phase 2: dataflow mma.sync scan (epoch-synchronized) =====
// CTA (q, jsl) owns 16 batches x 32 j. No per-step barrier: producers publish
// g_epoch[q][jsl] = t+1 (release) after writing h_t; consumers poll only the
// producers of the k-half they are about to stage. Skew is bounded to 1 step,
// which also serializes the h ping-pong buffer reuse (proof in header comment
// of quarter structure: X starts step t only after all quarter CTAs completed
// t-1, and publishes only after all its own reads are done).
#define SG 128
#define QCTAS 32

#define SMEM_WHI  0
#define SMEM_WLO  65536
#define SMEM_A    131072
#define SMEM_RED  196608
#define SMEM_TOT  198656

__device__ volatile unsigned g_epoch[128];     // [q*32 + jsl]; 0 at launch; reset at end
__device__ unsigned g_cnt4[4 * 32];            // endgame sense barriers (2 toggles/launch)
__device__ volatile unsigned g_sns4[4 * 32];

__device__ __forceinline__ void quarter_barrier(int tid, unsigned& sense, int q)
{
    __syncthreads();
    if (tid == 0) {
        __threadfence();
        unsigned s2 = sense ^ 1u;
        unsigned* cnt = &g_cnt4[q * 32];
        volatile unsigned* sns = &g_sns4[q * 32];
        unsigned old = atomicAdd(cnt, 1u);
        if (old == QCTAS - 1) {
            atomicExch(cnt, 0u);
            __threadfence();
            *sns = s2;
        } else {
            while (*sns != s2) { }
        }
        __threadfence();
    }
    sense ^= 1u;
    __syncthreads();
}

__global__ __launch_bounds__(256) void rnn_scan_mma(float* __restrict__ out)
{
    extern __shared__ __align__(1024) char sm[];
    const uint32_t smb = smem_u32(sm);
    const int tid  = threadIdx.x;
    const int w    = tid >> 5;
    const int lane = tid & 31;
    const int mi   = w >> 2;             // 0 = hi rows, 1 = lo rows
    const int ni   = w & 3;              // n-tile (8 j each)
    const int g    = lane >> 2;
    const int tt   = lane & 3;

    const int jsl  = blockIdx.x & 31;    // j-slice (producer id within quarter)
    const int j0   = jsl * 32;
    const int qid  = blockIdx.x >> 5;    // batch quarter 0..3
    const int b0   = qid * 16;

    // ---- W slice -> SMEM (resident all steps) ----
    {
        const uint4* s0 = (const uint4*)(g_Wh0 + (size_t)jsl * 65536);
        const uint4* s1 = (const uint4*)(g_Wh1 + (size_t)jsl * 65536);
        uint4* d0 = (uint4*)(sm + SMEM_WHI);
        uint4* d1 = (uint4*)(sm + SMEM_WLO);
        for (int i = tid; i < 4096; i += 256) { d0[i] = s0[i]; d1[i] = s1[i]; }
    }
    __syncthreads();

    // ldmatrix lane constants
    const int arow = mi * 16 + (lane & 15);                   // A row 0..31
    const uint32_t a_base = smb + SMEM_A + (uint32_t)arow * 2048;
    const uint32_t a_swz  = (uint32_t)(arow & 7) << 4;
    const int a_half = lane >> 4;
    const int jrow = lane & 7;
    const int bgran = lane >> 3;                              // 0..3
    const uint32_t bhi_base = smb + SMEM_WHI + (uint32_t)(ni * 8 + jrow) * 2048;
    const uint32_t blo_base = smb + SMEM_WLO + (uint32_t)(ni * 8 + jrow) * 2048;
    const uint32_t b_swz = (uint32_t)jrow << 4;

    float* red = (float*)(sm + SMEM_RED);
    unsigned sense = 0;

    // ---------- t = 0: h = tanh(xin); publish epoch 1 ----------
    {
        int lb = tid >> 4;                   // local batch 0..15
        int b  = b0 + lb;
        int jq = (tid & 15) * 2;
        int j  = j0 + jq;                    // global j (== A k index)
        size_t o = (size_t)b * (Tsz * Hsz) + j;
        float2 xv = *(const float2*)&out[o];
        float h0 = tanhf(xv.x), h1 = tanhf(xv.y);
        *(float2*)&out[o] = make_float2(h0, h1);
        __half a0 = __float2half_rn(h0), a1 = __float2half_rn(h1);
        __half2 hi2 = __halves2half2(a0, a1);
        *(__half2*)&g_hA[0][b * Hsz + j] = hi2;
        __half l0 = __float2half_rn(h0 - __half2float(a0));
        __half l1 = __float2half_rn(h1 - __half2float(a1));
        __half2 lo2 = __halves2half2(l0, l1);
        *(__half2*)&g_hA[0][(64 + b) * Hsz + j] = lo2;
        // own-slice shortcut: write straight into A smem for step 1
        uint32_t cbyte = (uint32_t)(j >> 3) << 4;
        uint32_t coff  = (uint32_t)((j & 7) * 2);
        *(__half2*)(sm + SMEM_A + (uint32_t)lb * 2048
                    + (cbyte ^ ((uint32_t)(lb & 7) << 4)) + coff) = hi2;
        int ml = 16 + lb;
        *(__half2*)(sm + SMEM_A + (uint32_t)ml * 2048
                    + (cbyte ^ ((uint32_t)(ml & 7) << 4)) + coff) = lo2;
    }
    __syncthreads();
    if (tid == 0) { __threadfence(); g_epoch[qid * 32 + jsl] = 1u; }

    // ---------- t = 1..511 ----------
    for (int t = 1; t < Tsz; t++) {
        const __half* hrd = g_hA[(t + 1) & 1];
        __half* hwr = g_hA[t & 1];

        // xin prefetch (independent of epochs)
        float2 xv0, xv1;
        size_t r0 = 0, r1 = 0;
        if (mi == 0) {
            int b = b0 + g;
            int col = j0 + ni * 8 + 2 * tt;
            r0 = ((size_t)b * Tsz + t) * Hsz + col;
            r1 = ((size_t)(b + 8) * Tsz + t) * Hsz + col;
            xv0 = *(const float2*)&out[r0];
            xv1 = *(const float2*)&out[r1];
        }

        // --- wait producers 0..15, stage k<512 (skip own slice) ---
        if (w == 0) {
            int p = lane;
            bool act = (lane < 16) && (p != jsl);
            bool ok;
            do {
                unsigned v = act ? g_epoch[qid * 32 + p] : (unsigned)t;
                ok = __all_sync(0xffffffffu, v >= (unsigned)t);
            } while (!ok);
        }
        __syncthreads();
        #pragma unroll
        for (int s = 0; s < 8; s++) {
            int gg = tid + (s << 8);          // 0..2047
            int m  = gg >> 6;                 // A row 0..31
            int c  = gg & 63;                 // granule (k<512)
            if ((c >> 2) != jsl) {
                int hrow = (m < 16) ? (b0 + m) : (48 + b0 + m);
                cp16(smb + SMEM_A + (uint32_t)m * 2048
                     + (((uint32_t)c * 16) ^ ((uint32_t)(m & 7) << 4)),
                     hrd + (size_t)hrow * Hsz + c * 8);
            }
        }
        CP_COMMIT();

        // --- wait producers 16..31, stage k>=512 (skip own slice) ---
        if (w == 0) {
            int p = 16 + lane;
            bool act = (lane < 16) && (p != jsl);
            bool ok;
            do {
                unsigned v = act ? g_epoch[qid * 32 + p] : (unsigned)t;
                ok = __all_sync(0xffffffffu, v >= (unsigned)t);
            } while (!ok);
        }
        __syncthreads();
        #pragma unroll
        for (int s = 0; s < 8; s++) {
            int gg = tid + (s << 8);
            int m  = gg >> 6;
            int c  = (gg & 63) + 64;          // granule (k>=512)
            if ((c >> 2) != jsl) {
                int hrow = (m < 16) ? (b0 + m) : (48 + b0 + m);
                cp16(smb + SMEM_A + (uint32_t)m * 2048
                     + (((uint32_t)c * 16) ^ ((uint32_t)(m & 7) << 4)),
                     hrd + (size_t)hrow * Hsz + c * 8);
            }
        }
        CP_COMMIT();

        float d[4] = {0, 0, 0, 0};

        // First half: k 0..511.
        CP_WAIT1();
        __syncthreads();
        #pragma unroll 8
        for (int ii = 0; ii < 16; ii++) {
            uint32_t kbyte = ((uint32_t)(4 * ii + bgran) * 16) ^ b_swz;
            uint32_t bh[4];
            ldsm4(bh, bhi_base + kbyte);
            uint32_t bl[4];
            if (mi == 0) ldsm4(bl, blo_base + kbyte);
            #pragma unroll
            for (int s2 = 0; s2 < 2; s2++) {
                int i = 2 * ii + s2;
                uint32_t a[4];
                ldsm4(a, a_base + (((uint32_t)(2 * i + a_half) * 16) ^ a_swz));
                mma16816(d, a, bh[2 * s2], bh[2 * s2 + 1]);
                if (mi == 0) mma16816(d, a, bl[2 * s2], bl[2 * s2 + 1]);
            }
        }
        // Second half: k 512..1023.
        CP_WAIT0();
        __syncthreads();
        #pragma unroll 8
        for (int ii = 16; ii < 32; ii++) {
            uint32_t kbyte = ((uint32_t)(4 * ii + bgran) * 16) ^ b_swz;
            uint32_t bh[4];
            ldsm4(bh, bhi_base + kbyte);
            uint32_t bl[4];
            if (mi == 0) ldsm4(bl, blo_base + kbyte);
            #pragma unroll
            for (int s2 = 0; s2 < 2; s2++) {
                int i = 2 * ii + s2;
                uint32_t a[4];
                ldsm4(a, a_base + (((uint32_t)(2 * i + a_half) * 16) ^ a_swz));
                mma16816(d, a, bh[2 * s2], bh[2 * s2 + 1]);
                if (mi == 0) mma16816(d, a, bl[2 * s2], bl[2 * s2 + 1]);
            }
        }

        // lo-row warps export partials (h_lo x W_hi)
        if (mi == 1) {
            *(float4*)&red[(ni * 32 + lane) * 4] = make_float4(d[0], d[1], d[2], d[3]);
        }
        __syncthreads();

        // hi-row warps: combine, tanh, write out + h splits (global + own-slice STS)
        if (mi == 0) {
            float4 rr = *(const float4*)&red[(ni * 32 + lane) * 4];

            float h00 = tanhf(xv0.x + d[0] + rr.x);
            float h01 = tanhf(xv0.y + d[1] + rr.y);
            float h10 = tanhf(xv1.x + d[2] + rr.z);
            float h11 = tanhf(xv1.y + d[3] + rr.w);

            *(float2*)&out[r0] = make_float2(h00, h01);
            *(float2*)&out[r1] = make_float2(h10, h11);

            if (t < Tsz - 1) {
                int b = b0 + g;
                int colj = j0 + ni * 8 + 2 * tt;          // global j == A k index
                uint32_t cbyte = (uint32_t)(colj >> 3) << 4;
                uint32_t coff  = (uint32_t)((colj & 7) * 2);
                auto emit = [&](float v0, float v1, int bb, int mrowHi) {
                    __half p0 = __float2half_rn(v0), p1 = __float2half_rn(v1);
                    __half2 hi2 = __halves2half2(p0, p1);
                    __half q0 = __float2half_rn(v0 - __half2float(p0));
                    __half q1 = __float2half_rn(v1 - __half2float(p1));
                    __half2 lo2 = __halves2half2(q0, q1);
                    *(__half2*)&hwr[bb * Hsz + colj]        = hi2;
                    *(__half2*)&hwr[(64 + bb) * Hsz + colj] = lo2;
                    int mh = mrowHi, mlr = 16 + mrowHi;
                    *(__half2*)(sm + SMEM_A + (uint32_t)mh * 2048
                                + (cbyte ^ ((uint32_t)(mh & 7) << 4)) + coff) = hi2;
                    *(__half2*)(sm + SMEM_A + (uint32_t)mlr * 2048
                                + (cbyte ^ ((uint32_t)(mlr & 7) << 4)) + coff) = lo2;
                };
                emit(h00, h01, b,     g);
                emit(h10, h11, b + 8, g + 8);
            }
        }
        __syncthreads();   // all h writes (global + STS) done CTA-wide

        if (tid == 0 && t < Tsz - 1) {
            __threadfence();                               // release h_t
            g_epoch[qid * 32 + jsl] = (unsigned)(t + 1);   // publish
        }
    }

    // ---------- endgame: replay-safe epoch reset (2 sense toggles) ----------
    quarter_barrier(tid, sense, qid);       // all quarter CTAs done reading epochs
    if (tid == 0) g_epoch[qid * 32 + jsl] = 0u;
    quarter_barrier(tid, sense, qid);       // even toggle count -> replay-safe
}

// ===================== launch =====================
extern "C" void kernel_launch(void* const* d_in, const int* in_sizes, int n_in,
                              void* d_out, int out_size)
{
    const float* x    = (const float*)d_in[0];   // [B,T,D]
    const float* Win  = (const float*)d_in[1];   // [H,D]
    const float* bin  = (const float*)d_in[2];   // [H]
    const float* Whh  = (const float*)d_in[3];   // [H,H]
    const float* bias = (const float*)d_in[4];   // [H]
    float* out = (float*)d_out;                  // [B,T,H]

    (void)in_sizes; (void)n_in; (void)out_size;

    cudaFuncSetAttribute(rnn_scan_mma,
                         cudaFuncAttributeMaxDynamicSharedMemorySize, SMEM_TOT);
    cudaFuncSetAttribute(gemm_in_mma,
                         cudaFuncAttributeMaxDynamicSharedMemorySize, P1_SMEM);

    // Prologues: splits (independent kernels)
    wsplit_kernel<<<Hsz, 256>>>(Whh);
    xsplit_kernel<<<16384, 256>>>(x);
    winsplit_kernel<<<512, 256>>>(Win);

    // Phase 1: xin -> out (tensor cores)
    dim3 grid1(8, 256);                          // (N-tiles, M-tiles)
    gemm_in_mma<<<grid1, 256, P1_SMEM>>>(bin, bias, out);

    // Phase 2: dataflow tensor-core recurrent scan
    rnn_scan_mma<<<SG, 256, SMEM_TOT>>>(out);
}